// round 8
// baseline (speedup 1.0000x reference)
#include <cuda_runtime.h>
#include <cuda_fp16.h>
#include <cstdint>

// ---------------------------------------------------------------------------
// CLIPDecoder_83786222011049 — single-head MHA forward.
// Round 8: BM=64 x BN=128 tiles, 256 threads, 3 CTAs/SM (24 warps/SM) for
// cross-CTA latency hiding. f16 3-split mma.sync + ldmatrix; fused softmax.
// ---------------------------------------------------------------------------

static constexpr int BM = 64, BN = 128, BK = 32;
static constexpr int A_T = 64 * 80;                 // 5120 B per A half-tile
static constexpr int B_T = 128 * 80;                // 10240 B per B half-tile
static constexpr int AH_O = 0, AL_O = A_T, BH_O = 2 * A_T, BL_O = 2 * A_T + B_T;
static constexpr int STAGE_B = 2 * A_T + 2 * B_T;   // 30720
static constexpr int SMEM_REQ = 2 * STAGE_B;        // 61440 -> 3 CTAs/SM

// ---------------------------------------------------------------------------
// Scratch (device globals).
// ---------------------------------------------------------------------------
#define BIGH (size_t)(16384) * 1024
#define BATH (size_t)(16) * 1024 * 1024
__device__ __align__(256) __half g_xq_h[BIGH], g_xq_l[BIGH];
__device__ __align__(256) __half g_xk_h[BIGH], g_xk_l[BIGH];
__device__ __align__(256) __half g_xv_h[BIGH], g_xv_l[BIGH];
__device__ __align__(256) __half g_wq_h[1024*1024], g_wq_l[1024*1024];
__device__ __align__(256) __half g_wk_h[1024*1024], g_wk_l[1024*1024];
__device__ __align__(256) __half g_wv_h[1024*1024], g_wv_l[1024*1024];
__device__ __align__(256) __half g_q_h[BIGH], g_q_l[BIGH];
__device__ __align__(256) __half g_k_h[BIGH], g_k_l[BIGH];
__device__ __align__(256) float  g_v[BIGH];
__device__ __align__(256) __half g_vt_h[BATH], g_vt_l[BATH];
__device__ __align__(256) __half g_a_h[BATH], g_a_l[BATH];
__device__ __align__(256) float  g_part[(size_t)16 * 1024 * 8];
__device__ __align__(256) float  g_rsum[(size_t)16 * 1024];

// ---------------------------------------------------------------------------
// PTX helpers
// ---------------------------------------------------------------------------
__device__ __forceinline__ void cp16(uint32_t sdst, const void* gsrc) {
    asm volatile("cp.async.cg.shared.global [%0], [%1], 16;\n"
                 :: "r"(sdst), "l"(gsrc));
}
__device__ __forceinline__ void cp_commit() {
    asm volatile("cp.async.commit_group;\n" ::: "memory");
}
template <int N> __device__ __forceinline__ void cp_wait() {
    asm volatile("cp.async.wait_group %0;\n" :: "n"(N) : "memory");
}
__device__ __forceinline__ void ldsm4(uint32_t* r, uint32_t addr) {
    asm volatile("ldmatrix.sync.aligned.m8n8.x4.shared.b16 {%0,%1,%2,%3}, [%4];"
                 : "=r"(r[0]), "=r"(r[1]), "=r"(r[2]), "=r"(r[3]) : "r"(addr));
}
__device__ __forceinline__ void mma16(float* d, const uint32_t* a, const uint32_t* b) {
    asm volatile(
        "mma.sync.aligned.m16n8k16.row.col.f32.f16.f16.f32 "
        "{%0,%1,%2,%3},{%4,%5,%6,%7},{%8,%9},{%0,%1,%2,%3};\n"
        : "+f"(d[0]), "+f"(d[1]), "+f"(d[2]), "+f"(d[3])
        : "r"(a[0]), "r"(a[1]), "r"(a[2]), "r"(a[3]), "r"(b[0]), "r"(b[1]));
}
__device__ __forceinline__ uint32_t pk2h(float a, float b) {
    __half2 t = __floats2half2_rn(a, b);
    return *reinterpret_cast<uint32_t*>(&t);
}

extern __shared__ char dynsm[];

// ---------------------------------------------------------------------------
// Generic GEMM (NT): D = Ah*Bh^T + Al*Bh^T + Ah*Bl^T.
// batched==0: blockIdx.z selects operand set. batched==1: z = batch index.
// mode: 0 fp32 out (+bias), 1 split out (+bias),
//       2 exp epilogue + row-sum partials, 3 fp32 out * rsum[row].
// ---------------------------------------------------------------------------
struct GArgs {
    const __half* Ah[3]; const __half* Al[3];
    const __half* Bh[3]; const __half* Bl[3];
    float* Cf[3]; __half* Ch[3]; __half* Cl[3];
    const float* bias[3];
    int mode[3];
    long long lda, ldb, ldc;
    long long sA, sB, sC;
    int K, batched;
    float ascale;
    float* part;
    const float* rsum;
};

__global__ __launch_bounds__(256, 3) void gemm_f16(GArgs p)
{
    const uint32_t sbase = (uint32_t)__cvta_generic_to_shared(dynsm);
    const int tid = threadIdx.x, lane = tid & 31, warp = tid >> 5;
    const int wm = warp & 1, wn = warp >> 1;      // 2(m) x 4(n) warps, 32x32 tiles
    const int q = lane & 3, g = lane >> 2;

    const int zi = p.batched ? 0 : (int)blockIdx.z;
    const long long bz = p.batched ? (long long)blockIdx.z : 0;
    const int mode = p.mode[zi];

    const long long m0 = (long long)blockIdx.y * BM;
    const long long n0 = (long long)blockIdx.x * BN;

    const char* Ahb = (const char*)(p.Ah[zi] + bz * p.sA + m0 * p.lda);
    const char* Alb = (const char*)(p.Al[zi] + bz * p.sA + m0 * p.lda);
    const char* Bhb = (const char*)(p.Bh[zi] + bz * p.sB + n0 * p.ldb);
    const char* Blb = (const char*)(p.Bl[zi] + bz * p.sB + n0 * p.ldb);

    const uint32_t aoff = (uint32_t)((wm * 32 + (lane & 15)) * 80 + ((lane >> 4) << 4));
    const uint32_t boff = (uint32_t)((wn * 32 + ((lane >> 4) & 1) * 8 + (lane & 7)) * 80
                                     + ((lane >> 3) & 1) * 16);

    float acc[2][4][4];
    #pragma unroll
    for (int i = 0; i < 2; ++i)
        #pragma unroll
        for (int j = 0; j < 4; ++j)
            #pragma unroll
            for (int r = 0; r < 4; ++r) acc[i][j][r] = 0.0f;

    const int KT = p.K / BK;
    const long long lda2 = p.lda * 2, ldb2 = p.ldb * 2;

    auto load_tile = [&](int kt) {
        const uint32_t sb = sbase + (kt & 1) * STAGE_B;
        const long long kb = (long long)kt * (BK * 2);
        const int row = tid >> 2, c = (tid & 3) * 16;
        // A: 64 rows, 1 chunk/thread per half
        {
            const uint32_t d = (uint32_t)(row * 80 + c);
            const long long ga = (long long)row * lda2 + kb + c;
            cp16(sb + AH_O + d, Ahb + ga);
            cp16(sb + AL_O + d, Alb + ga);
        }
        // B: 128 rows, 2 chunks/thread per half
        #pragma unroll
        for (int pp = 0; pp < 2; ++pp) {
            const int r = row + pp * 64;
            const uint32_t d = (uint32_t)(r * 80 + c);
            const long long gb = (long long)r * ldb2 + kb + c;
            cp16(sb + BH_O + d, Bhb + gb);
            cp16(sb + BL_O + d, Blb + gb);
        }
        cp_commit();
    };

    auto compute = [&](int kt) {
        const uint32_t sb = sbase + (kt & 1) * STAGE_B;
        #pragma unroll
        for (int kk = 0; kk < 2; ++kk) {
            const uint32_t ka = kk * 32;
            uint32_t ah[2][4], al[2][4];
            #pragma unroll
            for (int i = 0; i < 2; ++i) {
                ldsm4(ah[i], sb + AH_O + aoff + i * 1280 + ka);
                ldsm4(al[i], sb + AL_O + aoff + i * 1280 + ka);
            }
            uint32_t bh[4][2], bl[4][2];
            #pragma unroll
            for (int jp = 0; jp < 2; ++jp) {
                uint32_t rb[4];
                ldsm4(rb, sb + BH_O + boff + jp * 1280 + ka);
                bh[2*jp][0] = rb[0]; bh[2*jp][1] = rb[1];
                bh[2*jp+1][0] = rb[2]; bh[2*jp+1][1] = rb[3];
                ldsm4(rb, sb + BL_O + boff + jp * 1280 + ka);
                bl[2*jp][0] = rb[0]; bl[2*jp][1] = rb[1];
                bl[2*jp+1][0] = rb[2]; bl[2*jp+1][1] = rb[3];
            }
            #pragma unroll
            for (int i = 0; i < 2; ++i)
                #pragma unroll
                for (int j = 0; j < 4; ++j) {
                    mma16(acc[i][j], ah[i], bh[j]);
                    mma16(acc[i][j], al[i], bh[j]);
                    mma16(acc[i][j], ah[i], bl[j]);
                }
        }
    };

    load_tile(0);
    for (int kt = 0; kt < KT; ++kt) {
        cp_wait<0>();
        __syncthreads();
        if (kt + 1 < KT) load_tile(kt + 1);
        compute(kt);
    }

    // ---------------- epilogues ----------------
    if (mode == 2) {
        __syncthreads();                           // tiles dead; reuse smem
        float (*srows)[4] = reinterpret_cast<float(*)[4]>(dynsm);
        __half* Ch = p.Ch[zi]; __half* Cl = p.Cl[zi];
        #pragma unroll
        for (int i = 0; i < 2; ++i) {
            float p0 = 0.0f, p1 = 0.0f;
            const long long r0 = m0 + wm * 32 + i * 16 + g;
            #pragma unroll
            for (int j = 0; j < 4; ++j) {
                float e0 = __expf(acc[i][j][0] * p.ascale);
                float e1 = __expf(acc[i][j][1] * p.ascale);
                float e2 = __expf(acc[i][j][2] * p.ascale);
                float e3 = __expf(acc[i][j][3] * p.ascale);
                p0 += e0 + e1;  p1 += e2 + e3;
                const long long c0 = n0 + wn * 32 + j * 8 + 2 * q;
                __half h0 = __float2half_rn(e0), h1 = __float2half_rn(e1);
                __half h2 = __float2half_rn(e2), h3 = __float2half_rn(e3);
                float l0 = e0 - __half2float(h0), l1 = e1 - __half2float(h1);
                float l2 = e2 - __half2float(h2), l3 = e3 - __half2float(h3);
                *(uint32_t*)(Ch + bz * p.sC + r0 * p.ldc + c0)       = pk2h(e0, e1);
                *(uint32_t*)(Ch + bz * p.sC + (r0 + 8) * p.ldc + c0) = pk2h(e2, e3);
                *(uint32_t*)(Cl + bz * p.sC + r0 * p.ldc + c0)       = pk2h(l0, l1);
                *(uint32_t*)(Cl + bz * p.sC + (r0 + 8) * p.ldc + c0) = pk2h(l2, l3);
            }
            p0 += __shfl_xor_sync(0xFFFFFFFFu, p0, 1);
            p0 += __shfl_xor_sync(0xFFFFFFFFu, p0, 2);
            p1 += __shfl_xor_sync(0xFFFFFFFFu, p1, 1);
            p1 += __shfl_xor_sync(0xFFFFFFFFu, p1, 2);
            if (q == 0) {
                srows[wm * 32 + i * 16 + g][wn]     = p0;
                srows[wm * 32 + i * 16 + g + 8][wn] = p1;
            }
        }
        __syncthreads();
        if (tid < 64) {
            float s = srows[tid][0] + srows[tid][1] + srows[tid][2] + srows[tid][3];
            p.part[((bz << 10) + m0 + tid) * 8 + blockIdx.x] = s;
        }
        return;
    }

    if (mode == 3) {
        float* Cf = p.Cf[zi];
        #pragma unroll
        for (int i = 0; i < 2; ++i) {
            const long long r0 = m0 + wm * 32 + i * 16 + g;
            const float rs0 = p.rsum[(bz << 10) + r0];
            const float rs1 = p.rsum[(bz << 10) + r0 + 8];
            #pragma unroll
            for (int j = 0; j < 4; ++j) {
                const long long c0 = n0 + wn * 32 + j * 8 + 2 * q;
                *(float2*)(Cf + bz * p.sC + r0 * p.ldc + c0) =
                    make_float2(acc[i][j][0] * rs0, acc[i][j][1] * rs0);
                *(float2*)(Cf + bz * p.sC + (r0 + 8) * p.ldc + c0) =
                    make_float2(acc[i][j][2] * rs1, acc[i][j][3] * rs1);
            }
        }
        return;
    }

    const float* bias = p.bias[zi];
    #pragma unroll
    for (int i = 0; i < 2; ++i) {
        const long long r0 = m0 + wm * 32 + i * 16 + g;
        #pragma unroll
        for (int j = 0; j < 4; ++j) {
            const long long c0 = n0 + wn * 32 + j * 8 + 2 * q;
            const float b0 = bias ? bias[c0]     : 0.0f;
            const float b1 = bias ? bias[c0 + 1] : 0.0f;
            float x0 = acc[i][j][0] * p.ascale + b0;
            float x1 = acc[i][j][1] * p.ascale + b1;
            float x2 = acc[i][j][2] * p.ascale + b0;
            float x3 = acc[i][j][3] * p.ascale + b1;
            if (mode == 0) {
                float* Cf = p.Cf[zi];
                *(float2*)(Cf + bz * p.sC + r0 * p.ldc + c0)       = make_float2(x0, x1);
                *(float2*)(Cf + bz * p.sC + (r0 + 8) * p.ldc + c0) = make_float2(x2, x3);
            } else {
                __half* Ch = p.Ch[zi]; __half* Cl = p.Cl[zi];
                __half h0 = __float2half_rn(x0), h1 = __float2half_rn(x1);
                __half h2 = __float2half_rn(x2), h3 = __float2half_rn(x3);
                float l0 = x0 - __half2float(h0), l1 = x1 - __half2float(h1);
                float l2 = x2 - __half2float(h2), l3 = x3 - __half2float(h3);
                *(uint32_t*)(Ch + bz * p.sC + r0 * p.ldc + c0)       = pk2h(x0, x1);
                *(uint32_t*)(Ch + bz * p.sC + (r0 + 8) * p.ldc + c0) = pk2h(x2, x3);
                *(uint32_t*)(Cl + bz * p.sC + r0 * p.ldc + c0)       = pk2h(l0, l1);
                *(uint32_t*)(Cl + bz * p.sC + (r0 + 8) * p.ldc + c0) = pk2h(l2, l3);
            }
        }
    }
}

// ---------------------------------------------------------------------------
// fp32 -> (hi, lo) f16 split of x*scale; 3 arrays fused via blockIdx.y.
// ---------------------------------------------------------------------------
struct SplitArgs {
    const float* x[3];
    __half* h[3];
    __half* l[3];
};

__global__ __launch_bounds__(256) void split3_kernel(SplitArgs args, float scale)
{
    const int a = blockIdx.y;
    const long long i = (long long)blockIdx.x * 256 + threadIdx.x;
    float4 v = ((const float4*)args.x[a])[i];
    v.x *= scale; v.y *= scale; v.z *= scale; v.w *= scale;
    __half h0 = __float2half_rn(v.x), h1 = __float2half_rn(v.y);
    __half h2 = __float2half_rn(v.z), h3 = __float2half_rn(v.w);
    float l0 = v.x - __half2float(h0), l1 = v.y - __half2float(h1);
    float l2 = v.z - __half2float(h2), l3 = v.w - __half2float(h3);
    ((uint2*)args.h[a])[i] = make_uint2(pk2h(v.x, v.y), pk2h(v.z, v.w));
    ((uint2*)args.l[a])[i] = make_uint2(pk2h(l0, l1), pk2h(l2, l3));
}

// ---------------------------------------------------------------------------
// Transpose + split V:  v[(s*16+nb)*1024 + f] (fp32) -> vt{h,l}[nb][f][s]
// ---------------------------------------------------------------------------
__global__ __launch_bounds__(256) void transpose_split_kernel(
    const float* __restrict__ v, __half* __restrict__ vth,
    __half* __restrict__ vtl)
{
    __shared__ float t[64][65];
    const int nb = blockIdx.z;
    const int s0 = blockIdx.x * 64, f0 = blockIdx.y * 64;
    const int c = threadIdx.x & 63, r0 = threadIdx.x >> 6;

    #pragma unroll
    for (int rr = r0; rr < 64; rr += 4)
        t[rr][c] = v[(long long)((s0 + rr) * 16 + nb) * 1024 + f0 + c];
    __syncthreads();

    __half* oh = vth + (size_t)nb * 1024 * 1024;
    __half* ol = vtl + (size_t)nb * 1024 * 1024;
    #pragma unroll
    for (int rr = r0; rr < 64; rr += 4) {
        float x = t[c][rr];
        __half h = __float2half_rn(x);
        float lo = x - __half2float(h);
        size_t idx = (size_t)(f0 + rr) * 1024 + s0 + c;
        oh[idx] = h;
        ol[idx] = __float2half_rn(lo);
    }
}

// ---------------------------------------------------------------------------
// rsum[row] = 1 / sum_{cb<8} part[row*8+cb]
// ---------------------------------------------------------------------------
__global__ __launch_bounds__(256) void rowsum_kernel(
    const float* __restrict__ part, float* __restrict__ rsum)
{
    const int row = blockIdx.x * 256 + threadIdx.x;
    const float4 a = ((const float4*)part)[row * 2];
    const float4 b = ((const float4*)part)[row * 2 + 1];
    rsum[row] = 1.0f / (((a.x + a.y) + (a.z + a.w)) + ((b.x + b.y) + (b.z + b.w)));
}

// ---------------------------------------------------------------------------
// Launch
// ---------------------------------------------------------------------------
extern "C" void kernel_launch(void* const* d_in, const int* in_sizes, int n_in,
                              void* d_out, int out_size)
{
    const float* query = (const float*)d_in[0];
    const float* key   = (const float*)d_in[1];
    const float* value = (const float*)d_in[2];
    const float* wq    = (const float*)d_in[3];
    const float* wk    = (const float*)d_in[4];
    const float* wv    = (const float*)d_in[5];
    const float* bias  = (const float*)d_in[6];
    float* out = (float*)d_out;

    __half *xqh,*xql,*xkh,*xkl,*xvh,*xvl;
    __half *wqh,*wql,*wkh,*wkl,*wvh,*wvl;
    __half *qh,*ql,*kh,*kl,*vth,*vtl,*ath,*atl;
    float *vf, *part, *rsum;
    cudaGetSymbolAddress((void**)&xqh, g_xq_h); cudaGetSymbolAddress((void**)&xql, g_xq_l);
    cudaGetSymbolAddress((void**)&xkh, g_xk_h); cudaGetSymbolAddress((void**)&xkl, g_xk_l);
    cudaGetSymbolAddress((void**)&xvh, g_xv_h); cudaGetSymbolAddress((void**)&xvl, g_xv_l);
    cudaGetSymbolAddress((void**)&wqh, g_wq_h); cudaGetSymbolAddress((void**)&wql, g_wq_l);
    cudaGetSymbolAddress((void**)&wkh, g_wk_h); cudaGetSymbolAddress((void**)&wkl, g_wk_l);
    cudaGetSymbolAddress((void**)&wvh, g_wv_h); cudaGetSymbolAddress((void**)&wvl, g_wv_l);
    cudaGetSymbolAddress((void**)&qh,  g_q_h);  cudaGetSymbolAddress((void**)&ql,  g_q_l);
    cudaGetSymbolAddress((void**)&kh,  g_k_h);  cudaGetSymbolAddress((void**)&kl,  g_k_l);
    cudaGetSymbolAddress((void**)&vth, g_vt_h); cudaGetSymbolAddress((void**)&vtl, g_vt_l);
    cudaGetSymbolAddress((void**)&ath, g_a_h);  cudaGetSymbolAddress((void**)&atl, g_a_l);
    cudaGetSymbolAddress((void**)&vf,  g_v);
    cudaGetSymbolAddress((void**)&part, g_part);
    cudaGetSymbolAddress((void**)&rsum, g_rsum);

    cudaFuncSetAttribute(gemm_f16, cudaFuncAttributeMaxDynamicSharedMemorySize, SMEM_REQ);

    const long long MM = 1024LL * 1024;

    // 1) splits
    {
        SplitArgs in;
        in.x[0] = query; in.h[0] = xqh; in.l[0] = xql;
        in.x[1] = key;   in.h[1] = xkh; in.l[1] = xkl;
        in.x[2] = value; in.h[2] = xvh; in.l[2] = xvl;
        split3_kernel<<<dim3(16384, 3), 256>>>(in, 1.0f);
        SplitArgs w;
        w.x[0] = wq; w.h[0] = wqh; w.l[0] = wql;
        w.x[1] = wk; w.h[1] = wkh; w.l[1] = wkl;
        w.x[2] = wv; w.h[2] = wvh; w.l[2] = wvl;
        split3_kernel<<<dim3(1024, 3), 256>>>(w, 32.0f);
    }

    // 2) merged projections: f = acc/32 + bias
    {
        GArgs a = {};
        a.Ah[0] = xqh; a.Al[0] = xql; a.Bh[0] = wqh; a.Bl[0] = wql;
        a.Ah[1] = xkh; a.Al[1] = xkl; a.Bh[1] = wkh; a.Bl[1] = wkl;
        a.Ah[2] = xvh; a.Al[2] = xvl; a.Bh[2] = wvh; a.Bl[2] = wvl;
        a.Ch[0] = qh; a.Cl[0] = ql;
        a.Ch[1] = kh; a.Cl[1] = kl;
        a.Cf[2] = vf;
        a.bias[0] = bias; a.bias[1] = bias + 1024; a.bias[2] = bias + 2048;
        a.mode[0] = 1; a.mode[1] = 1; a.mode[2] = 0;
        a.lda = 1024; a.ldb = 1024; a.ldc = 1024;
        a.sA = 0; a.sB = 0; a.sC = 0;
        a.K = 1024; a.batched = 0; a.ascale = 1.0f / 32.0f;
        gemm_f16<<<dim3(8, 256, 3), 256, SMEM_REQ>>>(a);
    }

    // 3) V transpose + split
    transpose_split_kernel<<<dim3(16, 16, 16), 256>>>(vf, vth, vtl);

    // 4) scores + fused exp/partial-rowsum
    {
        GArgs a = {};
        a.Ah[0] = qh; a.Al[0] = ql; a.Bh[0] = kh; a.Bl[0] = kl;
        a.Ch[0] = ath; a.Cl[0] = atl;
        a.mode[0] = 2;
        a.lda = 16384; a.ldb = 16384; a.ldc = 1024;
        a.sA = 1024; a.sB = 1024; a.sC = MM;
        a.K = 1024; a.batched = 1; a.ascale = 1.0f / 32.0f;
        a.part = part;
        gemm_f16<<<dim3(8, 16, 16), 256, SMEM_REQ>>>(a);
    }

    // 5) row-sum reciprocal
    rowsum_kernel<<<64, 256>>>(part, rsum);

    // 6) out = (e @ vt^T) * rsum[row]
    {
        GArgs a = {};
        a.Ah[0] = ath; a.Al[0] = atl; a.Bh[0] = vth; a.Bl[0] = vtl;
        a.Cf[0] = out;
        a.mode[0] = 3;
        a.lda = 1024; a.ldb = 1024; a.ldc = 16384;
        a.sA = MM; a.sB = MM; a.sC = 1024;
        a.K = 1024; a.batched = 1; a.ascale = 1.0f;
        a.rsum = rsum;
        gemm_f16<<<dim3(8, 16, 16), 256, SMEM_REQ>>>(a);
    }
}

// round 9
// speedup vs baseline: 1.1022x; 1.1022x over previous
#include <cuda_runtime.h>
#include <cuda_fp16.h>
#include <cstdint>

// ---------------------------------------------------------------------------
// CLIPDecoder_83786222011049 — single-head MHA forward.
// Round 9: round-7 config (BM=BN=128, 8 warps, 2 CTAs/SM) with SW64-swizzled
// 64B SMEM rows (no padding) -> 3 pipeline stages (prefetch distance 2).
// f16 3-split mma.sync + ldmatrix; fused exp/rowsum softmax.
// ---------------------------------------------------------------------------

static constexpr int BM = 128, BN = 128, BK = 32;
static constexpr int TILE_B  = 128 * 64;            // 8192 B per matrix-half
static constexpr int AH_O = 0, AL_O = TILE_B, BH_O = 2 * TILE_B, BL_O = 3 * TILE_B;
static constexpr int STAGE_B = 4 * TILE_B;          // 32768
static constexpr int SMEM_REQ = 3 * STAGE_B;        // 98304 -> 2 CTAs/SM

// ---------------------------------------------------------------------------
// Scratch (device globals).
// ---------------------------------------------------------------------------
#define BIGH (size_t)(16384) * 1024
#define BATH (size_t)(16) * 1024 * 1024
__device__ __align__(256) __half g_xq_h[BIGH], g_xq_l[BIGH];
__device__ __align__(256) __half g_xk_h[BIGH], g_xk_l[BIGH];
__device__ __align__(256) __half g_xv_h[BIGH], g_xv_l[BIGH];
__device__ __align__(256) __half g_wq_h[1024*1024], g_wq_l[1024*1024];
__device__ __align__(256) __half g_wk_h[1024*1024], g_wk_l[1024*1024];
__device__ __align__(256) __half g_wv_h[1024*1024], g_wv_l[1024*1024];
__device__ __align__(256) __half g_q_h[BIGH], g_q_l[BIGH];
__device__ __align__(256) __half g_k_h[BIGH], g_k_l[BIGH];
__device__ __align__(256) float  g_v[BIGH];
__device__ __align__(256) __half g_vt_h[BATH], g_vt_l[BATH];
__device__ __align__(256) __half g_a_h[BATH], g_a_l[BATH];
__device__ __align__(256) float  g_part[(size_t)16 * 1024 * 8];
__device__ __align__(256) float  g_rsum[(size_t)16 * 1024];

// ---------------------------------------------------------------------------
// PTX helpers
// ---------------------------------------------------------------------------
__device__ __forceinline__ void cp16(uint32_t sdst, const void* gsrc) {
    asm volatile("cp.async.cg.shared.global [%0], [%1], 16;\n"
                 :: "r"(sdst), "l"(gsrc));
}
__device__ __forceinline__ void cp_commit() {
    asm volatile("cp.async.commit_group;\n" ::: "memory");
}
template <int N> __device__ __forceinline__ void cp_wait() {
    asm volatile("cp.async.wait_group %0;\n" :: "n"(N) : "memory");
}
__device__ __forceinline__ void ldsm4(uint32_t* r, uint32_t addr) {
    asm volatile("ldmatrix.sync.aligned.m8n8.x4.shared.b16 {%0,%1,%2,%3}, [%4];"
                 : "=r"(r[0]), "=r"(r[1]), "=r"(r[2]), "=r"(r[3]) : "r"(addr));
}
__device__ __forceinline__ void mma16(float* d, const uint32_t* a, const uint32_t* b) {
    asm volatile(
        "mma.sync.aligned.m16n8k16.row.col.f32.f16.f16.f32 "
        "{%0,%1,%2,%3},{%4,%5,%6,%7},{%8,%9},{%0,%1,%2,%3};\n"
        : "+f"(d[0]), "+f"(d[1]), "+f"(d[2]), "+f"(d[3])
        : "r"(a[0]), "r"(a[1]), "r"(a[2]), "r"(a[3]), "r"(b[0]), "r"(b[1]));
}
__device__ __forceinline__ uint32_t pk2h(float a, float b) {
    __half2 t = __floats2half2_rn(a, b);
    return *reinterpret_cast<uint32_t*>(&t);
}

extern __shared__ char dynsm[];

// ---------------------------------------------------------------------------
// Generic GEMM (NT): D = Ah*Bh^T + Al*Bh^T + Ah*Bl^T.
// batched==0: blockIdx.z selects operand set. batched==1: z = batch index.
// mode: 0 fp32 out (+bias), 1 split out (+bias),
//       2 exp epilogue + row-sum partials, 3 fp32 out * rsum[row].
// SMEM layout: 64B rows, SW64 swizzle: byte16-col ^ ((row&6)<<3).
// ---------------------------------------------------------------------------
struct GArgs {
    const __half* Ah[3]; const __half* Al[3];
    const __half* Bh[3]; const __half* Bl[3];
    float* Cf[3]; __half* Ch[3]; __half* Cl[3];
    const float* bias[3];
    int mode[3];
    long long lda, ldb, ldc;
    long long sA, sB, sC;
    int K, batched;
    float ascale;
    float* part;
    const float* rsum;
};

__global__ __launch_bounds__(256, 2) void gemm_f16(GArgs p)
{
    const uint32_t sbase = (uint32_t)__cvta_generic_to_shared(dynsm);
    const int tid = threadIdx.x, lane = tid & 31, warp = tid >> 5;
    const int wm = warp & 1, wn = warp >> 1;      // 2(m) x 4(n) warps
    const int q = lane & 3, g = lane >> 2;

    const int zi = p.batched ? 0 : (int)blockIdx.z;
    const long long bz = p.batched ? (long long)blockIdx.z : 0;
    const int mode = p.mode[zi];

    const long long m0 = (long long)blockIdx.y * BM;
    const long long n0 = (long long)blockIdx.x * BN;

    const char* Ahb = (const char*)(p.Ah[zi] + bz * p.sA + m0 * p.lda);
    const char* Alb = (const char*)(p.Al[zi] + bz * p.sA + m0 * p.lda);
    const char* Bhb = (const char*)(p.Bh[zi] + bz * p.sB + n0 * p.ldb);
    const char* Blb = (const char*)(p.Bl[zi] + bz * p.sB + n0 * p.ldb);

    // ldmatrix lane addressing (SW64): addr = row*64 + (ka ^ cs) + frag*1024
    const int a_row = wm * 64 + (lane & 15);
    const uint32_t a_base = (uint32_t)(a_row * 64);
    const uint32_t a_cs = (uint32_t)(((lane >> 4) << 4) ^ ((a_row & 6) << 3));
    const int b_row = wn * 32 + ((lane >> 4) & 1) * 8 + (lane & 7);
    const uint32_t b_base = (uint32_t)(b_row * 64);
    const uint32_t b_cs = (uint32_t)((((lane >> 3) & 1) << 4) ^ ((b_row & 6) << 3));

    float acc[4][4][4];
    #pragma unroll
    for (int i = 0; i < 4; ++i)
        #pragma unroll
        for (int j = 0; j < 4; ++j)
            #pragma unroll
            for (int r = 0; r < 4; ++r) acc[i][j][r] = 0.0f;

    const int KT = p.K / BK;
    const long long lda2 = p.lda * 2, ldb2 = p.ldb * 2;

    // store-side swizzle: row = tid>>2 (+64), c16 = (tid&3)*16
    const int srow = tid >> 2;
    const uint32_t sc16 = (uint32_t)(((tid & 3) << 4) ^ ((srow & 6) << 3));

    auto load_tile = [&](int kt) {
        const uint32_t sb = sbase + (kt % 3) * STAGE_B;
        const long long kb = (long long)kt * (BK * 2);
        #pragma unroll
        for (int pp = 0; pp < 2; ++pp) {
            const int r = srow + pp * 64;
            const uint32_t d = (uint32_t)(r * 64) + sc16;
            const long long ga = (long long)r * lda2 + kb + ((tid & 3) << 4);
            const long long gb = (long long)r * ldb2 + kb + ((tid & 3) << 4);
            cp16(sb + AH_O + d, Ahb + ga);
            cp16(sb + AL_O + d, Alb + ga);
            cp16(sb + BH_O + d, Bhb + gb);
            cp16(sb + BL_O + d, Blb + gb);
        }
        cp_commit();
    };

    auto compute = [&](int kt) {
        const uint32_t sb = sbase + (kt % 3) * STAGE_B;
        #pragma unroll
        for (int kk = 0; kk < 2; ++kk) {
            const uint32_t ka = kk * 32;
            const uint32_t aoff = a_base + (ka ^ a_cs);
            const uint32_t boff = b_base + (ka ^ b_cs);
            uint32_t ah[4][4], al[4][4];
            #pragma unroll
            for (int i = 0; i < 4; ++i) {
                ldsm4(ah[i], sb + AH_O + aoff + i * 1024);
                ldsm4(al[i], sb + AL_O + aoff + i * 1024);
            }
            uint32_t bh[4][2], bl[4][2];
            #pragma unroll
            for (int jp = 0; jp < 2; ++jp) {
                uint32_t rb[4];
                ldsm4(rb, sb + BH_O + boff + jp * 1024);
                bh[2*jp][0] = rb[0]; bh[2*jp][1] = rb[1];
                bh[2*jp+1][0] = rb[2]; bh[2*jp+1][1] = rb[3];
                ldsm4(rb, sb + BL_O + boff + jp * 1024);
                bl[2*jp][0] = rb[0]; bl[2*jp][1] = rb[1];
                bl[2*jp+1][0] = rb[2]; bl[2*jp+1][1] = rb[3];
            }
            #pragma unroll
            for (int i = 0; i < 4; ++i)
                #pragma unroll
                for (int j = 0; j < 4; ++j) {
                    mma16(acc[i][j], ah[i], bh[j]);
                    mma16(acc[i][j], al[i], bh[j]);
                    mma16(acc[i][j], ah[i], bl[j]);
                }
        }
    };

    // 3-stage pipeline, prefetch distance 2.
    load_tile(0);
    load_tile(1);
    for (int kt = 0; kt < KT; ++kt) {
        cp_wait<1>();          // tile kt resident (one younger group may fly)
        __syncthreads();
        if (kt + 2 < KT) load_tile(kt + 2);
        else             cp_commit();     // keep group accounting aligned
        compute(kt);
    }

    // ---------------- epilogues ----------------
    if (mode == 2) {
        __syncthreads();                           // tiles dead; reuse smem
        float (*srows)[4] = reinterpret_cast<float(*)[4]>(dynsm);
        __half* Ch = p.Ch[zi]; __half* Cl = p.Cl[zi];
        #pragma unroll
        for (int i = 0; i < 4; ++i) {
            float p0 = 0.0f, p1 = 0.0f;
            const long long r0 = m0 + wm * 64 + i * 16 + g;
            #pragma unroll
            for (int j = 0; j < 4; ++j) {
                float e0 = __expf(acc[i][j][0] * p.ascale);
                float e1 = __expf(acc[i][j][1] * p.ascale);
                float e2 = __expf(acc[i][j][2] * p.ascale);
                float e3 = __expf(acc[i][j][3] * p.ascale);
                p0 += e0 + e1;  p1 += e2 + e3;
                const long long c0 = n0 + wn * 32 + j * 8 + 2 * q;
                __half h0 = __float2half_rn(e0), h1 = __float2half_rn(e1);
                __half h2 = __float2half_rn(e2), h3 = __float2half_rn(e3);
                float l0 = e0 - __half2float(h0), l1 = e1 - __half2float(h1);
                float l2 = e2 - __half2float(h2), l3 = e3 - __half2float(h3);
                *(uint32_t*)(Ch + bz * p.sC + r0 * p.ldc + c0)       = pk2h(e0, e1);
                *(uint32_t*)(Ch + bz * p.sC + (r0 + 8) * p.ldc + c0) = pk2h(e2, e3);
                *(uint32_t*)(Cl + bz * p.sC + r0 * p.ldc + c0)       = pk2h(l0, l1);
                *(uint32_t*)(Cl + bz * p.sC + (r0 + 8) * p.ldc + c0) = pk2h(l2, l3);
            }
            p0 += __shfl_xor_sync(0xFFFFFFFFu, p0, 1);
            p0 += __shfl_xor_sync(0xFFFFFFFFu, p0, 2);
            p1 += __shfl_xor_sync(0xFFFFFFFFu, p1, 1);
            p1 += __shfl_xor_sync(0xFFFFFFFFu, p1, 2);
            if (q == 0) {
                srows[wm * 64 + i * 16 + g][wn]     = p0;
                srows[wm * 64 + i * 16 + g + 8][wn] = p1;
            }
        }
        __syncthreads();
        if (tid < 128) {
            float s = srows[tid][0] + srows[tid][1] + srows[tid][2] + srows[tid][3];
            p.part[((bz << 10) + m0 + tid) * 8 + blockIdx.x] = s;
        }
        return;
    }

    if (mode == 3) {
        float* Cf = p.Cf[zi];
        #pragma unroll
        for (int i = 0; i < 4; ++i) {
            const long long r0 = m0 + wm * 64 + i * 16 + g;
            const float rs0 = p.rsum[(bz << 10) + r0];
            const float rs1 = p.rsum[(bz << 10) + r0 + 8];
            #pragma unroll
            for (int j = 0; j < 4; ++j) {
                const long long c0 = n0 + wn * 32 + j * 8 + 2 * q;
                *(float2*)(Cf + bz * p.sC + r0 * p.ldc + c0) =
                    make_float2(acc[i][j][0] * rs0, acc[i][j][1] * rs0);
                *(float2*)(Cf + bz * p.sC + (r0 + 8) * p.ldc + c0) =
                    make_float2(acc[i][j][2] * rs1, acc[i][j][3] * rs1);
            }
        }
        return;
    }

    const float* bias = p.bias[zi];
    #pragma unroll
    for (int i = 0; i < 4; ++i) {
        const long long r0 = m0 + wm * 64 + i * 16 + g;
        #pragma unroll
        for (int j = 0; j < 4; ++j) {
            const long long c0 = n0 + wn * 32 + j * 8 + 2 * q;
            const float b0 = bias ? bias[c0]     : 0.0f;
            const float b1 = bias ? bias[c0 + 1] : 0.0f;
            float x0 = acc[i][j][0] * p.ascale + b0;
            float x1 = acc[i][j][1] * p.ascale + b1;
            float x2 = acc[i][j][2] * p.ascale + b0;
            float x3 = acc[i][j][3] * p.ascale + b1;
            if (mode == 0) {
                float* Cf = p.Cf[zi];
                *(float2*)(Cf + bz * p.sC + r0 * p.ldc + c0)       = make_float2(x0, x1);
                *(float2*)(Cf + bz * p.sC + (r0 + 8) * p.ldc + c0) = make_float2(x2, x3);
            } else {
                __half* Ch = p.Ch[zi]; __half* Cl = p.Cl[zi];
                __half h0 = __float2half_rn(x0), h1 = __float2half_rn(x1);
                __half h2 = __float2half_rn(x2), h3 = __float2half_rn(x3);
                float l0 = x0 - __half2float(h0), l1 = x1 - __half2float(h1);
                float l2 = x2 - __half2float(h2), l3 = x3 - __half2float(h3);
                *(uint32_t*)(Ch + bz * p.sC + r0 * p.ldc + c0)       = pk2h(x0, x1);
                *(uint32_t*)(Ch + bz * p.sC + (r0 + 8) * p.ldc + c0) = pk2h(x2, x3);
                *(uint32_t*)(Cl + bz * p.sC + r0 * p.ldc + c0)       = pk2h(l0, l1);
                *(uint32_t*)(Cl + bz * p.sC + (r0 + 8) * p.ldc + c0) = pk2h(l2, l3);
            }
        }
    }
}

// ---------------------------------------------------------------------------
// fp32 -> (hi, lo) f16 split of x*scale; 3 arrays fused via blockIdx.y.
// ---------------------------------------------------------------------------
struct SplitArgs {
    const float* x[3];
    __half* h[3];
    __half* l[3];
};

__global__ __launch_bounds__(256) void split3_kernel(SplitArgs args, float scale)
{
    const int a = blockIdx.y;
    const long long i = (long long)blockIdx.x * 256 + threadIdx.x;
    float4 v = ((const float4*)args.x[a])[i];
    v.x *= scale; v.y *= scale; v.z *= scale; v.w *= scale;
    __half h0 = __float2half_rn(v.x), h1 = __float2half_rn(v.y);
    __half h2 = __float2half_rn(v.z), h3 = __float2half_rn(v.w);
    float l0 = v.x - __half2float(h0), l1 = v.y - __half2float(h1);
    float l2 = v.z - __half2float(h2), l3 = v.w - __half2float(h3);
    ((uint2*)args.h[a])[i] = make_uint2(pk2h(v.x, v.y), pk2h(v.z, v.w));
    ((uint2*)args.l[a])[i] = make_uint2(pk2h(l0, l1), pk2h(l2, l3));
}

// ---------------------------------------------------------------------------
// Transpose + split V:  v[(s*16+nb)*1024 + f] (fp32) -> vt{h,l}[nb][f][s]
// ---------------------------------------------------------------------------
__global__ __launch_bounds__(256) void transpose_split_kernel(
    const float* __restrict__ v, __half* __restrict__ vth,
    __half* __restrict__ vtl)
{
    __shared__ float t[64][65];
    const int nb = blockIdx.z;
    const int s0 = blockIdx.x * 64, f0 = blockIdx.y * 64;
    const int c = threadIdx.x & 63, r0 = threadIdx.x >> 6;

    #pragma unroll
    for (int rr = r0; rr < 64; rr += 4)
        t[rr][c] = v[(long long)((s0 + rr) * 16 + nb) * 1024 + f0 + c];
    __syncthreads();

    __half* oh = vth + (size_t)nb * 1024 * 1024;
    __half* ol = vtl + (size_t)nb * 1024 * 1024;
    #pragma unroll
    for (int rr = r0; rr < 64; rr += 4) {
        float x = t[c][rr];
        __half h = __float2half_rn(x);
        float lo = x - __half2float(h);
        size_t idx = (size_t)(f0 + rr) * 1024 + s0 + c;
        oh[idx] = h;
        ol[idx] = __float2half_rn(lo);
    }
}

// ---------------------------------------------------------------------------
// rsum[row] = 1 / sum_{cb<8} part[row*8+cb]
// ---------------------------------------------------------------------------
__global__ __launch_bounds__(256) void rowsum_kernel(
    const float* __restrict__ part, float* __restrict__ rsum)
{
    const int row = blockIdx.x * 256 + threadIdx.x;
    const float4 a = ((const float4*)part)[row * 2];
    const float4 b = ((const float4*)part)[row * 2 + 1];
    rsum[row] = 1.0f / (((a.x + a.y) + (a.z + a.w)) + ((b.x + b.y) + (b.z + b.w)));
}

// ---------------------------------------------------------------------------
// Launch
// ---------------------------------------------------------------------------
extern "C" void kernel_launch(void* const* d_in, const int* in_sizes, int n_in,
                              void* d_out, int out_size)
{
    const float* query = (const float*)d_in[0];
    const float* key   = (const float*)d_in[1];
    const float* value = (const float*)d_in[2];
    const float* wq    = (const float*)d_in[3];
    const float* wk    = (const float*)d_in[4];
    const float* wv    = (const float*)d_in[5];
    const float* bias  = (const float*)d_in[6];
    float* out = (float*)d_out;

    __half *xqh,*xql,*xkh,*xkl,*xvh,*xvl;
    __half *wqh,*wql,*wkh,*wkl,*wvh,*wvl;
    __half *qh,*ql,*kh,*kl,*vth,*vtl,*ath,*atl;
    float *vf, *part, *rsum;
    cudaGetSymbolAddress((void**)&xqh, g_xq_h); cudaGetSymbolAddress((void**)&xql, g_xq_l);
    cudaGetSymbolAddress((void**)&xkh, g_xk_h); cudaGetSymbolAddress((void**)&xkl, g_xk_l);
    cudaGetSymbolAddress((void**)&xvh, g_xv_h); cudaGetSymbolAddress((void**)&xvl, g_xv_l);
    cudaGetSymbolAddress((void**)&wqh, g_wq_h); cudaGetSymbolAddress((void**)&wql, g_wq_l);
    cudaGetSymbolAddress((void**)&wkh, g_wk_h); cudaGetSymbolAddress((void**)&wkl, g_wk_l);
    cudaGetSymbolAddress((void**)&wvh, g_wv_h); cudaGetSymbolAddress((void**)&wvl, g_wv_l);
    cudaGetSymbolAddress((void**)&qh,  g_q_h);  cudaGetSymbolAddress((void**)&ql,  g_q_l);
    cudaGetSymbolAddress((void**)&kh,  g_k_h);  cudaGetSymbolAddress((void**)&kl,  g_k_l);
    cudaGetSymbolAddress((void**)&vth, g_vt_h); cudaGetSymbolAddress((void**)&vtl, g_vt_l);
    cudaGetSymbolAddress((void**)&ath, g_a_h);  cudaGetSymbolAddress((void**)&atl, g_a_l);
    cudaGetSymbolAddress((void**)&vf,  g_v);
    cudaGetSymbolAddress((void**)&part, g_part);
    cudaGetSymbolAddress((void**)&rsum, g_rsum);

    cudaFuncSetAttribute(gemm_f16, cudaFuncAttributeMaxDynamicSharedMemorySize, SMEM_REQ);

    const long long MM = 1024LL * 1024;

    // 1) splits
    {
        SplitArgs in;
        in.x[0] = query; in.h[0] = xqh; in.l[0] = xql;
        in.x[1] = key;   in.h[1] = xkh; in.l[1] = xkl;
        in.x[2] = value; in.h[2] = xvh; in.l[2] = xvl;
        split3_kernel<<<dim3(16384, 3), 256>>>(in, 1.0f);
        SplitArgs w;
        w.x[0] = wq; w.h[0] = wqh; w.l[0] = wql;
        w.x[1] = wk; w.h[1] = wkh; w.l[1] = wkl;
        w.x[2] = wv; w.h[2] = wvh; w.l[2] = wvl;
        split3_kernel<<<dim3(1024, 3), 256>>>(w, 32.0f);
    }

    // 2) merged projections: f = acc/32 + bias
    {
        GArgs a = {};
        a.Ah[0] = xqh; a.Al[0] = xql; a.Bh[0] = wqh; a.Bl[0] = wql;
        a.Ah[1] = xkh; a.Al[1] = xkl; a.Bh[1] = wkh; a.Bl[1] = wkl;
        a.Ah[2] = xvh; a.Al[2] = xvl; a.Bh[2] = wvh; a.Bl[2] = wvl;
        a.Ch[0] = qh; a.Cl[0] = ql;
        a.Ch[1] = kh; a.Cl[1] = kl;
        a.Cf[2] = vf;
        a.bias[0] = bias; a.bias[1] = bias + 1024; a.bias[2] = bias + 2048;
        a.mode[0] = 1; a.mode[1] = 1; a.mode[2] = 0;
        a.lda = 1024; a.ldb = 1024; a.ldc = 1024;
        a.sA = 0; a.sB = 0; a.sC = 0;
        a.K = 1024; a.batched = 0; a.ascale = 1.0f / 32.0f;
        gemm_f16<<<dim3(8, 128, 3), 256, SMEM_REQ>>>(a);
    }

    // 3) V transpose + split
    transpose_split_kernel<<<dim3(16, 16, 16), 256>>>(vf, vth, vtl);

    // 4) scores + fused exp/partial-rowsum
    {
        GArgs a = {};
        a.Ah[0] = qh; a.Al[0] = ql; a.Bh[0] = kh; a.Bl[0] = kl;
        a.Ch[0] = ath; a.Cl[0] = atl;
        a.mode[0] = 2;
        a.lda = 16384; a.ldb = 16384; a.ldc = 1024;
        a.sA = 1024; a.sB = 1024; a.sC = MM;
        a.K = 1024; a.batched = 1; a.ascale = 1.0f / 32.0f;
        a.part = part;
        gemm_f16<<<dim3(8, 8, 16), 256, SMEM_REQ>>>(a);
    }

    // 5) row-sum reciprocal
    rowsum_kernel<<<64, 256>>>(part, rsum);

    // 6) out = (e @ vt^T) * rsum[row]
    {
        GArgs a = {};
        a.Ah[0] = ath; a.Al[0] = atl; a.Bh[0] = vth; a.Bl[0] = vtl;
        a.Cf[0] = out;
        a.mode[0] = 3;
        a.lda = 1024; a.ldb = 1024; a.ldc = 16384;
        a.sA = MM; a.sB = MM; a.sC = 1024;
        a.K = 1024; a.batched = 1; a.ascale = 1.0f;
        a.rsum = rsum;
        gemm_f16<<<dim3(8, 8, 16), 256, SMEM_REQ>>>(a);
    }
}

// round 10
// speedup vs baseline: 1.3123x; 1.1905x over previous
#include <cuda_runtime.h>
#include <cuda_fp16.h>
#include <cstdint>

// ---------------------------------------------------------------------------
// CLIPDecoder_83786222011049 — single-head MHA forward.
// Round 10: 3-term f16 split projections; 2-term (A-hi only) scores and AV
// GEMMs (error budget allows it: predicted rel_err ~3e-4 < 1e-3).
// q/k stored batch-major for contiguous scores-GEMM loads. SW64 swizzle,
// 3-stage cp.async pipeline, ldmatrix, fused exp/rowsum softmax.
// ---------------------------------------------------------------------------

static constexpr int BM = 128, BN = 128, BK = 32;
static constexpr int TILE_B = 128 * 64;             // 8192 B per half-tile
static constexpr int SMEM3 = 3 * 4 * TILE_B;        // 98304 (Ah,Al,Bh,Bl)
static constexpr int SMEM2 = 3 * 3 * TILE_B;        // 73728 (Ah,Bh,Bl)

// ---------------------------------------------------------------------------
// Scratch (device globals).
// ---------------------------------------------------------------------------
#define BIGH (size_t)(16384) * 1024
#define BATH (size_t)(16) * 1024 * 1024
__device__ __align__(256) __half g_xq_h[BIGH], g_xq_l[BIGH];
__device__ __align__(256) __half g_xk_h[BIGH], g_xk_l[BIGH];
__device__ __align__(256) __half g_xv_h[BIGH], g_xv_l[BIGH];
__device__ __align__(256) __half g_wq_h[1024*1024], g_wq_l[1024*1024];
__device__ __align__(256) __half g_wk_h[1024*1024], g_wk_l[1024*1024];
__device__ __align__(256) __half g_wv_h[1024*1024], g_wv_l[1024*1024];
__device__ __align__(256) __half g_q_h[BIGH];                     // [nb][l][e]
__device__ __align__(256) __half g_k_h[BIGH], g_k_l[BIGH];        // [nb][l][e]
__device__ __align__(256) float  g_v[BIGH];
__device__ __align__(256) __half g_vt_h[BATH], g_vt_l[BATH];      // [nb][f][s]
__device__ __align__(256) __half g_a_h[BATH];                     // [nb][l][s]
__device__ __align__(256) float  g_part[(size_t)16 * 1024 * 8];
__device__ __align__(256) float  g_rsum[(size_t)16 * 1024];

// ---------------------------------------------------------------------------
// PTX helpers
// ---------------------------------------------------------------------------
__device__ __forceinline__ void cp16(uint32_t sdst, const void* gsrc) {
    asm volatile("cp.async.cg.shared.global [%0], [%1], 16;\n"
                 :: "r"(sdst), "l"(gsrc));
}
__device__ __forceinline__ void cp_commit() {
    asm volatile("cp.async.commit_group;\n" ::: "memory");
}
template <int N> __device__ __forceinline__ void cp_wait() {
    asm volatile("cp.async.wait_group %0;\n" :: "n"(N) : "memory");
}
__device__ __forceinline__ void ldsm4(uint32_t* r, uint32_t addr) {
    asm volatile("ldmatrix.sync.aligned.m8n8.x4.shared.b16 {%0,%1,%2,%3}, [%4];"
                 : "=r"(r[0]), "=r"(r[1]), "=r"(r[2]), "=r"(r[3]) : "r"(addr));
}
__device__ __forceinline__ void mma16(float* d, const uint32_t* a, const uint32_t* b) {
    asm volatile(
        "mma.sync.aligned.m16n8k16.row.col.f32.f16.f16.f32 "
        "{%0,%1,%2,%3},{%4,%5,%6,%7},{%8,%9},{%0,%1,%2,%3};\n"
        : "+f"(d[0]), "+f"(d[1]), "+f"(d[2]), "+f"(d[3])
        : "r"(a[0]), "r"(a[1]), "r"(a[2]), "r"(a[3]), "r"(b[0]), "r"(b[1]));
}
__device__ __forceinline__ uint32_t pk2h(float a, float b) {
    __half2 t = __floats2half2_rn(a, b);
    return *reinterpret_cast<uint32_t*>(&t);
}

extern __shared__ char dynsm[];

// ---------------------------------------------------------------------------
// GEMM (NT).  TERMS=3: D = Ah*Bh + Al*Bh + Ah*Bl.  TERMS=2: D = Ah*Bh + Ah*Bl.
// batched==0: blockIdx.z selects operand set. batched==1: z = batch index.
// mode: 0 fp32 out (+bias)
//       2 exp epilogue: hi-split out + row-sum partials
//       3 fp32 out * rsum[row]
//       4 hi/lo split out, batch-transposed [nb][l][e] (+bias)
//       5 hi-only out,  batch-transposed [nb][l][e] (+bias)
// SMEM: 64B rows, SW64 swizzle (byte16-col ^ ((row&6)<<3)).
// ---------------------------------------------------------------------------
struct GArgs {
    const __half* Ah[3]; const __half* Al[3];
    const __half* Bh[3]; const __half* Bl[3];
    float* Cf[3]; __half* Ch[3]; __half* Cl[3];
    const float* bias[3];
    int mode[3];
    long long lda, ldb, ldc;
    long long sA, sB, sC;
    int K, batched;
    float ascale;
    float* part;
    const float* rsum;
};

template <int TERMS>
__global__ __launch_bounds__(256, 2) void gemm_f16(GArgs p)
{
    constexpr int AH_O = 0;
    constexpr int AL_O = TILE_B;                          // only if TERMS==3
    constexpr int BH_O = (TERMS == 3) ? 2 * TILE_B : TILE_B;
    constexpr int BL_O = BH_O + TILE_B;
    constexpr int STAGE_B = (TERMS + 1) * TILE_B;

    const uint32_t sbase = (uint32_t)__cvta_generic_to_shared(dynsm);
    const int tid = threadIdx.x, lane = tid & 31, warp = tid >> 5;
    const int wm = warp & 1, wn = warp >> 1;      // 2(m) x 4(n) warps
    const int q = lane & 3, g = lane >> 2;

    const int zi = p.batched ? 0 : (int)blockIdx.z;
    const long long bz = p.batched ? (long long)blockIdx.z : 0;
    const int mode = p.mode[zi];

    const long long m0 = (long long)blockIdx.y * BM;
    const long long n0 = (long long)blockIdx.x * BN;

    const char* Ahb = (const char*)(p.Ah[zi] + bz * p.sA + m0 * p.lda);
    const char* Alb = (const char*)(p.Al[zi] + bz * p.sA + m0 * p.lda);
    const char* Bhb = (const char*)(p.Bh[zi] + bz * p.sB + n0 * p.ldb);
    const char* Blb = (const char*)(p.Bl[zi] + bz * p.sB + n0 * p.ldb);

    // ldmatrix lane addressing (SW64)
    const int a_row = wm * 64 + (lane & 15);
    const uint32_t a_base = (uint32_t)(a_row * 64);
    const uint32_t a_cs = (uint32_t)(((lane >> 4) << 4) ^ ((a_row & 6) << 3));
    const int b_row = wn * 32 + ((lane >> 4) & 1) * 8 + (lane & 7);
    const uint32_t b_base = (uint32_t)(b_row * 64);
    const uint32_t b_cs = (uint32_t)((((lane >> 3) & 1) << 4) ^ ((b_row & 6) << 3));

    float acc[4][4][4];
    #pragma unroll
    for (int i = 0; i < 4; ++i)
        #pragma unroll
        for (int j = 0; j < 4; ++j)
            #pragma unroll
            for (int r = 0; r < 4; ++r) acc[i][j][r] = 0.0f;

    const int KT = p.K / BK;
    const long long lda2 = p.lda * 2, ldb2 = p.ldb * 2;

    const int srow = tid >> 2;
    const uint32_t sc16 = (uint32_t)(((tid & 3) << 4) ^ ((srow & 6) << 3));

    auto load_tile = [&](int kt) {
        const uint32_t sb = sbase + (kt % 3) * STAGE_B;
        const long long kb = (long long)kt * (BK * 2);
        #pragma unroll
        for (int pp = 0; pp < 2; ++pp) {
            const int r = srow + pp * 64;
            const uint32_t d = (uint32_t)(r * 64) + sc16;
            const long long ga = (long long)r * lda2 + kb + ((tid & 3) << 4);
            const long long gb = (long long)r * ldb2 + kb + ((tid & 3) << 4);
            cp16(sb + AH_O + d, Ahb + ga);
            if (TERMS == 3) cp16(sb + AL_O + d, Alb + ga);
            cp16(sb + BH_O + d, Bhb + gb);
            cp16(sb + BL_O + d, Blb + gb);
        }
        cp_commit();
    };

    auto compute = [&](int kt) {
        const uint32_t sb = sbase + (kt % 3) * STAGE_B;
        #pragma unroll
        for (int kk = 0; kk < 2; ++kk) {
            const uint32_t ka = kk * 32;
            const uint32_t aoff = a_base + (ka ^ a_cs);
            const uint32_t boff = b_base + (ka ^ b_cs);
            uint32_t ah[4][4], al[4][4];
            #pragma unroll
            for (int i = 0; i < 4; ++i) {
                ldsm4(ah[i], sb + AH_O + aoff + i * 1024);
                if (TERMS == 3) ldsm4(al[i], sb + AL_O + aoff + i * 1024);
            }
            uint32_t bh[4][2], bl[4][2];
            #pragma unroll
            for (int jp = 0; jp < 2; ++jp) {
                uint32_t rb[4];
                ldsm4(rb, sb + BH_O + boff + jp * 1024);
                bh[2*jp][0] = rb[0]; bh[2*jp][1] = rb[1];
                bh[2*jp+1][0] = rb[2]; bh[2*jp+1][1] = rb[3];
                ldsm4(rb, sb + BL_O + boff + jp * 1024);
                bl[2*jp][0] = rb[0]; bl[2*jp][1] = rb[1];
                bl[2*jp+1][0] = rb[2]; bl[2*jp+1][1] = rb[3];
            }
            #pragma unroll
            for (int i = 0; i < 4; ++i)
                #pragma unroll
                for (int j = 0; j < 4; ++j) {
                    mma16(acc[i][j], ah[i], bh[j]);
                    if (TERMS == 3) mma16(acc[i][j], al[i], bh[j]);
                    mma16(acc[i][j], ah[i], bl[j]);
                }
        }
    };

    // 3-stage pipeline, prefetch distance 2.
    load_tile(0);
    load_tile(1);
    for (int kt = 0; kt < KT; ++kt) {
        cp_wait<1>();
        __syncthreads();
        if (kt + 2 < KT) load_tile(kt + 2);
        else             cp_commit();
        compute(kt);
    }

    // ---------------- epilogues ----------------
    if (mode == 2) {
        __syncthreads();
        float (*srows)[4] = reinterpret_cast<float(*)[4]>(dynsm);
        __half* Ch = p.Ch[zi];
        #pragma unroll
        for (int i = 0; i < 4; ++i) {
            float p0 = 0.0f, p1 = 0.0f;
            const long long r0 = m0 + wm * 64 + i * 16 + g;
            #pragma unroll
            for (int j = 0; j < 4; ++j) {
                float e0 = __expf(acc[i][j][0] * p.ascale);
                float e1 = __expf(acc[i][j][1] * p.ascale);
                float e2 = __expf(acc[i][j][2] * p.ascale);
                float e3 = __expf(acc[i][j][3] * p.ascale);
                p0 += e0 + e1;  p1 += e2 + e3;
                const long long c0 = n0 + wn * 32 + j * 8 + 2 * q;
                *(uint32_t*)(Ch + bz * p.sC + r0 * p.ldc + c0)       = pk2h(e0, e1);
                *(uint32_t*)(Ch + bz * p.sC + (r0 + 8) * p.ldc + c0) = pk2h(e2, e3);
            }
            p0 += __shfl_xor_sync(0xFFFFFFFFu, p0, 1);
            p0 += __shfl_xor_sync(0xFFFFFFFFu, p0, 2);
            p1 += __shfl_xor_sync(0xFFFFFFFFu, p1, 1);
            p1 += __shfl_xor_sync(0xFFFFFFFFu, p1, 2);
            if (q == 0) {
                srows[wm * 64 + i * 16 + g][wn]     = p0;
                srows[wm * 64 + i * 16 + g + 8][wn] = p1;
            }
        }
        __syncthreads();
        if (tid < 128) {
            float s = srows[tid][0] + srows[tid][1] + srows[tid][2] + srows[tid][3];
            p.part[((bz << 10) + m0 + tid) * 8 + blockIdx.x] = s;
        }
        return;
    }

    if (mode == 3) {
        float* Cf = p.Cf[zi];
        #pragma unroll
        for (int i = 0; i < 4; ++i) {
            const long long r0 = m0 + wm * 64 + i * 16 + g;
            const float rs0 = p.rsum[(bz << 10) + r0];
            const float rs1 = p.rsum[(bz << 10) + r0 + 8];
            #pragma unroll
            for (int j = 0; j < 4; ++j) {
                const long long c0 = n0 + wn * 32 + j * 8 + 2 * q;
                *(float2*)(Cf + bz * p.sC + r0 * p.ldc + c0) =
                    make_float2(acc[i][j][0] * rs0, acc[i][j][1] * rs0);
                *(float2*)(Cf + bz * p.sC + (r0 + 8) * p.ldc + c0) =
                    make_float2(acc[i][j][2] * rs1, acc[i][j][3] * rs1);
            }
        }
        return;
    }

    // modes 0 / 4 / 5: f = acc*ascale + bias
    const float* bias = p.bias[zi];
    #pragma unroll
    for (int i = 0; i < 4; ++i) {
        const long long r0 = m0 + wm * 64 + i * 16 + g;
        const long long r1 = r0 + 8;
        // batch-transposed addresses (modes 4/5): [nb][l][e]
        const long long t0 = ((r0 & 15) << 20) + ((r0 >> 4) << 10);
        const long long t1 = ((r1 & 15) << 20) + ((r1 >> 4) << 10);
        #pragma unroll
        for (int j = 0; j < 4; ++j) {
            const long long c0 = n0 + wn * 32 + j * 8 + 2 * q;
            const float b0 = bias ? bias[c0]     : 0.0f;
            const float b1 = bias ? bias[c0 + 1] : 0.0f;
            float x0 = acc[i][j][0] * p.ascale + b0;
            float x1 = acc[i][j][1] * p.ascale + b1;
            float x2 = acc[i][j][2] * p.ascale + b0;
            float x3 = acc[i][j][3] * p.ascale + b1;
            if (mode == 0) {
                float* Cf = p.Cf[zi];
                *(float2*)(Cf + r0 * p.ldc + c0) = make_float2(x0, x1);
                *(float2*)(Cf + r1 * p.ldc + c0) = make_float2(x2, x3);
            } else {
                __half* Ch = p.Ch[zi];
                *(uint32_t*)(Ch + t0 + c0) = pk2h(x0, x1);
                *(uint32_t*)(Ch + t1 + c0) = pk2h(x2, x3);
                if (mode == 4) {
                    __half* Cl = p.Cl[zi];
                    __half h0 = __float2half_rn(x0), h1 = __float2half_rn(x1);
                    __half h2 = __float2half_rn(x2), h3 = __float2half_rn(x3);
                    float l0 = x0 - __half2float(h0), l1 = x1 - __half2float(h1);
                    float l2 = x2 - __half2float(h2), l3 = x3 - __half2float(h3);
                    *(uint32_t*)(Cl + t0 + c0) = pk2h(l0, l1);
                    *(uint32_t*)(Cl + t1 + c0) = pk2h(l2, l3);
                }
            }
        }
    }
}

// ---------------------------------------------------------------------------
// fp32 -> (hi, lo) f16 split of x*scale; 3 arrays fused via blockIdx.y.
// ---------------------------------------------------------------------------
struct SplitArgs {
    const float* x[3];
    __half* h[3];
    __half* l[3];
};

__global__ __launch_bounds__(256) void split3_kernel(SplitArgs args, float scale)
{
    const int a = blockIdx.y;
    const long long i = (long long)blockIdx.x * 256 + threadIdx.x;
    float4 v = ((const float4*)args.x[a])[i];
    v.x *= scale; v.y *= scale; v.z *= scale; v.w *= scale;
    __half h0 = __float2half_rn(v.x), h1 = __float2half_rn(v.y);
    __half h2 = __float2half_rn(v.z), h3 = __float2half_rn(v.w);
    float l0 = v.x - __half2float(h0), l1 = v.y - __half2float(h1);
    float l2 = v.z - __half2float(h2), l3 = v.w - __half2float(h3);
    ((uint2*)args.h[a])[i] = make_uint2(pk2h(v.x, v.y), pk2h(v.z, v.w));
    ((uint2*)args.l[a])[i] = make_uint2(pk2h(l0, l1), pk2h(l2, l3));
}

// ---------------------------------------------------------------------------
// Transpose + split V:  v[(s*16+nb)*1024 + f] (fp32) -> vt{h,l}[nb][f][s]
// ---------------------------------------------------------------------------
__global__ __launch_bounds__(256) void transpose_split_kernel(
    const float* __restrict__ v, __half* __restrict__ vth,
    __half* __restrict__ vtl)
{
    __shared__ float t[64][65];
    const int nb = blockIdx.z;
    const int s0 = blockIdx.x * 64, f0 = blockIdx.y * 64;
    const int c = threadIdx.x & 63, r0 = threadIdx.x >> 6;

    #pragma unroll
    for (int rr = r0; rr < 64; rr += 4)
        t[rr][c] = v[(long long)((s0 + rr) * 16 + nb) * 1024 + f0 + c];
    __syncthreads();

    __half* oh = vth + (size_t)nb * 1024 * 1024;
    __half* ol = vtl + (size_t)nb * 1024 * 1024;
    #pragma unroll
    for (int rr = r0; rr < 64; rr += 4) {
        float x = t[c][rr];
        __half h = __float2half_rn(x);
        float lo = x - __half2float(h);
        size_t idx = (size_t)(f0 + rr) * 1024 + s0 + c;
        oh[idx] = h;
        ol[idx] = __float2half_rn(lo);
    }
}

// ---------------------------------------------------------------------------
// rsum[row] = 1 / sum_{cb<8} part[row*8+cb]
// ---------------------------------------------------------------------------
__global__ __launch_bounds__(256) void rowsum_kernel(
    const float* __restrict__ part, float* __restrict__ rsum)
{
    const int row = blockIdx.x * 256 + threadIdx.x;
    const float4 a = ((const float4*)part)[row * 2];
    const float4 b = ((const float4*)part)[row * 2 + 1];
    rsum[row] = 1.0f / (((a.x + a.y) + (a.z + a.w)) + ((b.x + b.y) + (b.z + b.w)));
}

// ---------------------------------------------------------------------------
// Launch
// ---------------------------------------------------------------------------
extern "C" void kernel_launch(void* const* d_in, const int* in_sizes, int n_in,
                              void* d_out, int out_size)
{
    const float* query = (const float*)d_in[0];
    const float* key   = (const float*)d_in[1];
    const float* value = (const float*)d_in[2];
    const float* wq    = (const float*)d_in[3];
    const float* wk    = (const float*)d_in[4];
    const float* wv    = (const float*)d_in[5];
    const float* bias  = (const float*)d_in[6];
    float* out = (float*)d_out;

    __half *xqh,*xql,*xkh,*xkl,*xvh,*xvl;
    __half *wqh,*wql,*wkh,*wkl,*wvh,*wvl;
    __half *qh,*kh,*kl,*vth,*vtl,*ath;
    float *vf, *part, *rsum;
    cudaGetSymbolAddress((void**)&xqh, g_xq_h); cudaGetSymbolAddress((void**)&xql, g_xq_l);
    cudaGetSymbolAddress((void**)&xkh, g_xk_h); cudaGetSymbolAddress((void**)&xkl, g_xk_l);
    cudaGetSymbolAddress((void**)&xvh, g_xv_h); cudaGetSymbolAddress((void**)&xvl, g_xv_l);
    cudaGetSymbolAddress((void**)&wqh, g_wq_h); cudaGetSymbolAddress((void**)&wql, g_wq_l);
    cudaGetSymbolAddress((void**)&wkh, g_wk_h); cudaGetSymbolAddress((void**)&wkl, g_wk_l);
    cudaGetSymbolAddress((void**)&wvh, g_wv_h); cudaGetSymbolAddress((void**)&wvl, g_wv_l);
    cudaGetSymbolAddress((void**)&qh,  g_q_h);
    cudaGetSymbolAddress((void**)&kh,  g_k_h);  cudaGetSymbolAddress((void**)&kl,  g_k_l);
    cudaGetSymbolAddress((void**)&vth, g_vt_h); cudaGetSymbolAddress((void**)&vtl, g_vt_l);
    cudaGetSymbolAddress((void**)&ath, g_a_h);
    cudaGetSymbolAddress((void**)&vf,  g_v);
    cudaGetSymbolAddress((void**)&part, g_part);
    cudaGetSymbolAddress((void**)&rsum, g_rsum);

    cudaFuncSetAttribute(gemm_f16<3>, cudaFuncAttributeMaxDynamicSharedMemorySize, SMEM3);
    cudaFuncSetAttribute(gemm_f16<2>, cudaFuncAttributeMaxDynamicSharedMemorySize, SMEM2);

    const long long MM = 1024LL * 1024;

    // 1) splits
    {
        SplitArgs in;
        in.x[0] = query; in.h[0] = xqh; in.l[0] = xql;
        in.x[1] = key;   in.h[1] = xkh; in.l[1] = xkl;
        in.x[2] = value; in.h[2] = xvh; in.l[2] = xvl;
        split3_kernel<<<dim3(16384, 3), 256>>>(in, 1.0f);
        SplitArgs w;
        w.x[0] = wq; w.h[0] = wqh; w.l[0] = wql;
        w.x[1] = wk; w.h[1] = wkh; w.l[1] = wkl;
        w.x[2] = wv; w.h[2] = wvh; w.l[2] = wvl;
        split3_kernel<<<dim3(1024, 3), 256>>>(w, 32.0f);
    }

    // 2) merged projections (3-term): f = acc/32 + bias
    //    q -> hi-only batch-major (mode 5); k -> hi/lo batch-major (mode 4);
    //    v -> fp32 row-major (mode 0).
    {
        GArgs a = {};
        a.Ah[0] = xqh; a.Al[0] = xql; a.Bh[0] = wqh; a.Bl[0] = wql;
        a.Ah[1] = xkh; a.Al[1] = xkl; a.Bh[1] = wkh; a.Bl[1] = wkl;
        a.Ah[2] = xvh; a.Al[2] = xvl; a.Bh[2] = wvh; a.Bl[2] = wvl;
        a.Ch[0] = qh;
        a.Ch[1] = kh; a.Cl[1] = kl;
        a.Cf[2] = vf;
        a.bias[0] = bias; a.bias[1] = bias + 1024; a.bias[2] = bias + 2048;
        a.mode[0] = 5; a.mode[1] = 4; a.mode[2] = 0;
        a.lda = 1024; a.ldb = 1024; a.ldc = 1024;
        a.sA = 0; a.sB = 0; a.sC = 0;
        a.K = 1024; a.batched = 0; a.ascale = 1.0f / 32.0f;
        gemm_f16<3><<<dim3(8, 128, 3), 256, SMEM3>>>(a);
    }

    // 3) V transpose + split
    transpose_split_kernel<<<dim3(16, 16, 16), 256>>>(vf, vth, vtl);

    // 4) scores (2-term: qh*kh + qh*kl) + fused exp/partial-rowsum
    {
        GArgs a = {};
        a.Ah[0] = qh; a.Bh[0] = kh; a.Bl[0] = kl;
        a.Ch[0] = ath;
        a.mode[0] = 2;
        a.lda = 1024; a.ldb = 1024; a.ldc = 1024;
        a.sA = 1LL << 20; a.sB = 1LL << 20; a.sC = MM;
        a.K = 1024; a.batched = 1; a.ascale = 1.0f / 32.0f;
        a.part = part;
        gemm_f16<2><<<dim3(8, 8, 16), 256, SMEM2>>>(a);
    }

    // 5) row-sum reciprocal
    rowsum_kernel<<<64, 256>>>(part, rsum);

    // 6) out = (e @ vt^T) * rsum[row]  (2-term: ah*vh + ah*vl)
    {
        GArgs a = {};
        a.Ah[0] = ath; a.Bh[0] = vth; a.Bl[0] = vtl;
        a.Cf[0] = out;
        a.mode[0] = 3;
        a.lda = 1024; a.ldb = 1024; a.ldc = 16384;
        a.sA = MM; a.sB = MM; a.sC = 1024;
        a.K = 1024; a.batched = 1; a.ascale = 1.0f;
        a.rsum = rsum;
        gemm_f16<2><<<dim3(8, 8, 16), 256, SMEM2>>>(a);
    }
}

// round 11
// speedup vs baseline: 1.6718x; 1.2739x over previous
#include <cuda_runtime.h>
#include <cuda_fp16.h>
#include <cstdint>

// ---------------------------------------------------------------------------
// CLIPDecoder_83786222011049 — single-head MHA forward.
// Round 11: ALL GEMMs 2-term asymmetric f16 split (A hi-only, B hi+lo).
// Calibrated error model: each dropped lo-term ~1.4e-4 -> predicted ~4.5e-4.
// q/k batch-major; SW64 swizzle; 3-stage cp.async; ldmatrix; fused softmax.
// ---------------------------------------------------------------------------

static constexpr int BM = 128, BN = 128, BK = 32;
static constexpr int TILE_B = 128 * 64;             // 8192 B per half-tile
static constexpr int STAGE_B = 3 * TILE_B;          // Ah, Bh, Bl
static constexpr int SMEM_REQ = 3 * STAGE_B;        // 73728 -> 2 CTAs/SM

// ---------------------------------------------------------------------------
// Scratch (device globals).
// ---------------------------------------------------------------------------
#define BIGH (size_t)(16384) * 1024
#define BATH (size_t)(16) * 1024 * 1024
__device__ __align__(256) __half g_xq_h[BIGH];
__device__ __align__(256) __half g_xk_h[BIGH];
__device__ __align__(256) __half g_xv_h[BIGH];
__device__ __align__(256) __half g_wq_h[1024*1024], g_wq_l[1024*1024];
__device__ __align__(256) __half g_wk_h[1024*1024], g_wk_l[1024*1024];
__device__ __align__(256) __half g_wv_h[1024*1024], g_wv_l[1024*1024];
__device__ __align__(256) __half g_q_h[BIGH];                     // [nb][l][e]
__device__ __align__(256) __half g_k_h[BIGH], g_k_l[BIGH];        // [nb][l][e]
__device__ __align__(256) float  g_v[BIGH];
__device__ __align__(256) __half g_vt_h[BATH], g_vt_l[BATH];      // [nb][f][s]
__device__ __align__(256) __half g_a_h[BATH];                     // [nb][l][s]
__device__ __align__(256) float  g_part[(size_t)16 * 1024 * 8];
__device__ __align__(256) float  g_rsum[(size_t)16 * 1024];

// ---------------------------------------------------------------------------
// PTX helpers
// ---------------------------------------------------------------------------
__device__ __forceinline__ void cp16(uint32_t sdst, const void* gsrc) {
    asm volatile("cp.async.cg.shared.global [%0], [%1], 16;\n"
                 :: "r"(sdst), "l"(gsrc));
}
__device__ __forceinline__ void cp_commit() {
    asm volatile("cp.async.commit_group;\n" ::: "memory");
}
template <int N> __device__ __forceinline__ void cp_wait() {
    asm volatile("cp.async.wait_group %0;\n" :: "n"(N) : "memory");
}
__device__ __forceinline__ void ldsm4(uint32_t* r, uint32_t addr) {
    asm volatile("ldmatrix.sync.aligned.m8n8.x4.shared.b16 {%0,%1,%2,%3}, [%4];"
                 : "=r"(r[0]), "=r"(r[1]), "=r"(r[2]), "=r"(r[3]) : "r"(addr));
}
__device__ __forceinline__ void mma16(float* d, const uint32_t* a, const uint32_t* b) {
    asm volatile(
        "mma.sync.aligned.m16n8k16.row.col.f32.f16.f16.f32 "
        "{%0,%1,%2,%3},{%4,%5,%6,%7},{%8,%9},{%0,%1,%2,%3};\n"
        : "+f"(d[0]), "+f"(d[1]), "+f"(d[2]), "+f"(d[3])
        : "r"(a[0]), "r"(a[1]), "r"(a[2]), "r"(a[3]), "r"(b[0]), "r"(b[1]));
}
__device__ __forceinline__ uint32_t pk2h(float a, float b) {
    __half2 t = __floats2half2_rn(a, b);
    return *reinterpret_cast<uint32_t*>(&t);
}

extern __shared__ char dynsm[];

// ---------------------------------------------------------------------------
// GEMM (NT), 2-term: D = Ah*Bh + Ah*Bl.
// batched==0: blockIdx.z selects operand set. batched==1: z = batch index.
// mode: 0 fp32 out (+bias)
//       2 exp epilogue: hi out + row-sum partials
//       3 fp32 out * rsum[row]
//       4 hi/lo split out, batch-transposed [nb][l][e] (+bias)
//       5 hi-only out,  batch-transposed [nb][l][e] (+bias)
// SMEM: 64B rows, SW64 swizzle (byte16-col ^ ((row&6)<<3)).
// ---------------------------------------------------------------------------
struct GArgs {
    const __half* Ah[3];
    const __half* Bh[3]; const __half* Bl[3];
    float* Cf[3]; __half* Ch[3]; __half* Cl[3];
    const float* bias[3];
    int mode[3];
    long long lda, ldb, ldc;
    long long sA, sB, sC;
    int K, batched;
    float ascale;
    float* part;
    const float* rsum;
};

__global__ __launch_bounds__(256, 2) void gemm_f16(GArgs p)
{
    constexpr int AH_O = 0, BH_O = TILE_B, BL_O = 2 * TILE_B;

    const uint32_t sbase = (uint32_t)__cvta_generic_to_shared(dynsm);
    const int tid = threadIdx.x, lane = tid & 31, warp = tid >> 5;
    const int wm = warp & 1, wn = warp >> 1;      // 2(m) x 4(n) warps
    const int q = lane & 3, g = lane >> 2;

    const int zi = p.batched ? 0 : (int)blockIdx.z;
    const long long bz = p.batched ? (long long)blockIdx.z : 0;
    const int mode = p.mode[zi];

    const long long m0 = (long long)blockIdx.y * BM;
    const long long n0 = (long long)blockIdx.x * BN;

    const char* Ahb = (const char*)(p.Ah[zi] + bz * p.sA + m0 * p.lda);
    const char* Bhb = (const char*)(p.Bh[zi] + bz * p.sB + n0 * p.ldb);
    const char* Blb = (const char*)(p.Bl[zi] + bz * p.sB + n0 * p.ldb);

    // ldmatrix lane addressing (SW64)
    const int a_row = wm * 64 + (lane & 15);
    const uint32_t a_base = (uint32_t)(a_row * 64);
    const uint32_t a_cs = (uint32_t)(((lane >> 4) << 4) ^ ((a_row & 6) << 3));
    const int b_row = wn * 32 + ((lane >> 4) & 1) * 8 + (lane & 7);
    const uint32_t b_base = (uint32_t)(b_row * 64);
    const uint32_t b_cs = (uint32_t)((((lane >> 3) & 1) << 4) ^ ((b_row & 6) << 3));

    float acc[4][4][4];
    #pragma unroll
    for (int i = 0; i < 4; ++i)
        #pragma unroll
        for (int j = 0; j < 4; ++j)
            #pragma unroll
            for (int r = 0; r < 4; ++r) acc[i][j][r] = 0.0f;

    const int KT = p.K / BK;
    const long long lda2 = p.lda * 2, ldb2 = p.ldb * 2;

    const int srow = tid >> 2;
    const uint32_t sc16 = (uint32_t)(((tid & 3) << 4) ^ ((srow & 6) << 3));

    auto load_tile = [&](int kt) {
        const uint32_t sb = sbase + (kt % 3) * STAGE_B;
        const long long kb = (long long)kt * (BK * 2);
        #pragma unroll
        for (int pp = 0; pp < 2; ++pp) {
            const int r = srow + pp * 64;
            const uint32_t d = (uint32_t)(r * 64) + sc16;
            const long long ga = (long long)r * lda2 + kb + ((tid & 3) << 4);
            const long long gb = (long long)r * ldb2 + kb + ((tid & 3) << 4);
            cp16(sb + AH_O + d, Ahb + ga);
            cp16(sb + BH_O + d, Bhb + gb);
            cp16(sb + BL_O + d, Blb + gb);
        }
        cp_commit();
    };

    auto compute = [&](int kt) {
        const uint32_t sb = sbase + (kt % 3) * STAGE_B;
        #pragma unroll
        for (int kk = 0; kk < 2; ++kk) {
            const uint32_t ka = kk * 32;
            const uint32_t aoff = a_base + (ka ^ a_cs);
            const uint32_t boff = b_base + (ka ^ b_cs);
            uint32_t ah[4][4];
            #pragma unroll
            for (int i = 0; i < 4; ++i)
                ldsm4(ah[i], sb + AH_O + aoff + i * 1024);
            uint32_t bh[4][2], bl[4][2];
            #pragma unroll
            for (int jp = 0; jp < 2; ++jp) {
                uint32_t rb[4];
                ldsm4(rb, sb + BH_O + boff + jp * 1024);
                bh[2*jp][0] = rb[0]; bh[2*jp][1] = rb[1];
                bh[2*jp+1][0] = rb[2]; bh[2*jp+1][1] = rb[3];
                ldsm4(rb, sb + BL_O + boff + jp * 1024);
                bl[2*jp][0] = rb[0]; bl[2*jp][1] = rb[1];
                bl[2*jp+1][0] = rb[2]; bl[2*jp+1][1] = rb[3];
            }
            #pragma unroll
            for (int i = 0; i < 4; ++i)
                #pragma unroll
                for (int j = 0; j < 4; ++j) {
                    mma16(acc[i][j], ah[i], bh[j]);
                    mma16(acc[i][j], ah[i], bl[j]);
                }
        }
    };

    // 3-stage pipeline, prefetch distance 2.
    load_tile(0);
    load_tile(1);
    for (int kt = 0; kt < KT; ++kt) {
        cp_wait<1>();
        __syncthreads();
        if (kt + 2 < KT) load_tile(kt + 2);
        else             cp_commit();
        compute(kt);
    }

    // ---------------- epilogues ----------------
    if (mode == 2) {
        __syncthreads();
        float (*srows)[4] = reinterpret_cast<float(*)[4]>(dynsm);
        __half* Ch = p.Ch[zi];
        #pragma unroll
        for (int i = 0; i < 4; ++i) {
            float p0 = 0.0f, p1 = 0.0f;
            const long long r0 = m0 + wm * 64 + i * 16 + g;
            #pragma unroll
            for (int j = 0; j < 4; ++j) {
                float e0 = __expf(acc[i][j][0] * p.ascale);
                float e1 = __expf(acc[i][j][1] * p.ascale);
                float e2 = __expf(acc[i][j][2] * p.ascale);
                float e3 = __expf(acc[i][j][3] * p.ascale);
                p0 += e0 + e1;  p1 += e2 + e3;
                const long long c0 = n0 + wn * 32 + j * 8 + 2 * q;
                *(uint32_t*)(Ch + bz * p.sC + r0 * p.ldc + c0)       = pk2h(e0, e1);
                *(uint32_t*)(Ch + bz * p.sC + (r0 + 8) * p.ldc + c0) = pk2h(e2, e3);
            }
            p0 += __shfl_xor_sync(0xFFFFFFFFu, p0, 1);
            p0 += __shfl_xor_sync(0xFFFFFFFFu, p0, 2);
            p1 += __shfl_xor_sync(0xFFFFFFFFu, p1, 1);
            p1 += __shfl_xor_sync(0xFFFFFFFFu, p1, 2);
            if (q == 0) {
                srows[wm * 64 + i * 16 + g][wn]     = p0;
                srows[wm * 64 + i * 16 + g + 8][wn] = p1;
            }
        }
        __syncthreads();
        if (tid < 128) {
            float s = srows[tid][0] + srows[tid][1] + srows[tid][2] + srows[tid][3];
            p.part[((bz << 10) + m0 + tid) * 8 + blockIdx.x] = s;
        }
        return;
    }

    if (mode == 3) {
        float* Cf = p.Cf[zi];
        #pragma unroll
        for (int i = 0; i < 4; ++i) {
            const long long r0 = m0 + wm * 64 + i * 16 + g;
            const float rs0 = p.rsum[(bz << 10) + r0];
            const float rs1 = p.rsum[(bz << 10) + r0 + 8];
            #pragma unroll
            for (int j = 0; j < 4; ++j) {
                const long long c0 = n0 + wn * 32 + j * 8 + 2 * q;
                *(float2*)(Cf + bz * p.sC + r0 * p.ldc + c0) =
                    make_float2(acc[i][j][0] * rs0, acc[i][j][1] * rs0);
                *(float2*)(Cf + bz * p.sC + (r0 + 8) * p.ldc + c0) =
                    make_float2(acc[i][j][2] * rs1, acc[i][j][3] * rs1);
            }
        }
        return;
    }

    // modes 0 / 4 / 5: f = acc*ascale + bias
    const float* bias = p.bias[zi];
    #pragma unroll
    for (int i = 0; i < 4; ++i) {
        const long long r0 = m0 + wm * 64 + i * 16 + g;
        const long long r1 = r0 + 8;
        // batch-transposed addresses (modes 4/5): [nb][l][e]
        const long long t0 = ((r0 & 15) << 20) + ((r0 >> 4) << 10);
        const long long t1 = ((r1 & 15) << 20) + ((r1 >> 4) << 10);
        #pragma unroll
        for (int j = 0; j < 4; ++j) {
            const long long c0 = n0 + wn * 32 + j * 8 + 2 * q;
            const float b0 = bias ? bias[c0]     : 0.0f;
            const float b1 = bias ? bias[c0 + 1] : 0.0f;
            float x0 = acc[i][j][0] * p.ascale + b0;
            float x1 = acc[i][j][1] * p.ascale + b1;
            float x2 = acc[i][j][2] * p.ascale + b0;
            float x3 = acc[i][j][3] * p.ascale + b1;
            if (mode == 0) {
                float* Cf = p.Cf[zi];
                *(float2*)(Cf + r0 * p.ldc + c0) = make_float2(x0, x1);
                *(float2*)(Cf + r1 * p.ldc + c0) = make_float2(x2, x3);
            } else {
                __half* Ch = p.Ch[zi];
                *(uint32_t*)(Ch + t0 + c0) = pk2h(x0, x1);
                *(uint32_t*)(Ch + t1 + c0) = pk2h(x2, x3);
                if (mode == 4) {
                    __half* Cl = p.Cl[zi];
                    __half h0 = __float2half_rn(x0), h1 = __float2half_rn(x1);
                    __half h2 = __float2half_rn(x2), h3 = __float2half_rn(x3);
                    float l0 = x0 - __half2float(h0), l1 = x1 - __half2float(h1);
                    float l2 = x2 - __half2float(h2), l3 = x3 - __half2float(h3);
                    *(uint32_t*)(Cl + t0 + c0) = pk2h(l0, l1);
                    *(uint32_t*)(Cl + t1 + c0) = pk2h(l2, l3);
                }
            }
        }
    }
}

// ---------------------------------------------------------------------------
// fp32 -> f16 (hi only), 3 arrays fused via blockIdx.y.
// ---------------------------------------------------------------------------
struct ConvArgs {
    const float* x[3];
    __half* h[3];
};

__global__ __launch_bounds__(256) void convert3_kernel(ConvArgs args)
{
    const int a = blockIdx.y;
    const long long i = (long long)blockIdx.x * 256 + threadIdx.x;
    float4 v = ((const float4*)args.x[a])[i];
    ((uint2*)args.h[a])[i] = make_uint2(pk2h(v.x, v.y), pk2h(v.z, v.w));
}

// ---------------------------------------------------------------------------
// fp32 -> (hi, lo) f16 split of x*scale; 3 arrays fused via blockIdx.y.
// ---------------------------------------------------------------------------
struct SplitArgs {
    const float* x[3];
    __half* h[3];
    __half* l[3];
};

__global__ __launch_bounds__(256) void split3_kernel(SplitArgs args, float scale)
{
    const int a = blockIdx.y;
    const long long i = (long long)blockIdx.x * 256 + threadIdx.x;
    float4 v = ((const float4*)args.x[a])[i];
    v.x *= scale; v.y *= scale; v.z *= scale; v.w *= scale;
    __half h0 = __float2half_rn(v.x), h1 = __float2half_rn(v.y);
    __half h2 = __float2half_rn(v.z), h3 = __float2half_rn(v.w);
    float l0 = v.x - __half2float(h0), l1 = v.y - __half2float(h1);
    float l2 = v.z - __half2float(h2), l3 = v.w - __half2float(h3);
    ((uint2*)args.h[a])[i] = make_uint2(pk2h(v.x, v.y), pk2h(v.z, v.w));
    ((uint2*)args.l[a])[i] = make_uint2(pk2h(l0, l1), pk2h(l2, l3));
}

// ---------------------------------------------------------------------------
// Transpose + split V:  v[(s*16+nb)*1024 + f] (fp32) -> vt{h,l}[nb][f][s]
// ---------------------------------------------------------------------------
__global__ __launch_bounds__(256) void transpose_split_kernel(
    const float* __restrict__ v, __half* __restrict__ vth,
    __half* __restrict__ vtl)
{
    __shared__ float t[64][65];
    const int nb = blockIdx.z;
    const int s0 = blockIdx.x * 64, f0 = blockIdx.y * 64;
    const int c = threadIdx.x & 63, r0 = threadIdx.x >> 6;

    #pragma unroll
    for (int rr = r0; rr < 64; rr += 4)
        t[rr][c] = v[(long long)((s0 + rr) * 16 + nb) * 1024 + f0 + c];
    __syncthreads();

    __half* oh = vth + (size_t)nb * 1024 * 1024;
    __half* ol = vtl + (size_t)nb * 1024 * 1024;
    #pragma unroll
    for (int rr = r0; rr < 64; rr += 4) {
        float x = t[c][rr];
        __half h = __float2half_rn(x);
        float lo = x - __half2float(h);
        size_t idx = (size_t)(f0 + rr) * 1024 + s0 + c;
        oh[idx] = h;
        ol[idx] = __float2half_rn(lo);
    }
}

// ---------------------------------------------------------------------------
// rsum[row] = 1 / sum_{cb<8} part[row*8+cb]
// ---------------------------------------------------------------------------
__global__ __launch_bounds__(256) void rowsum_kernel(
    const float* __restrict__ part, float* __restrict__ rsum)
{
    const int row = blockIdx.x * 256 + threadIdx.x;
    const float4 a = ((const float4*)part)[row * 2];
    const float4 b = ((const float4*)part)[row * 2 + 1];
    rsum[row] = 1.0f / (((a.x + a.y) + (a.z + a.w)) + ((b.x + b.y) + (b.z + b.w)));
}

// ---------------------------------------------------------------------------
// Launch
// ---------------------------------------------------------------------------
extern "C" void kernel_launch(void* const* d_in, const int* in_sizes, int n_in,
                              void* d_out, int out_size)
{
    const float* query = (const float*)d_in[0];
    const float* key   = (const float*)d_in[1];
    const float* value = (const float*)d_in[2];
    const float* wq    = (const float*)d_in[3];
    const float* wk    = (const float*)d_in[4];
    const float* wv    = (const float*)d_in[5];
    const float* bias  = (const float*)d_in[6];
    float* out = (float*)d_out;

    __half *xqh,*xkh,*xvh;
    __half *wqh,*wql,*wkh,*wkl,*wvh,*wvl;
    __half *qh,*kh,*kl,*vth,*vtl,*ath;
    float *vf, *part, *rsum;
    cudaGetSymbolAddress((void**)&xqh, g_xq_h);
    cudaGetSymbolAddress((void**)&xkh, g_xk_h);
    cudaGetSymbolAddress((void**)&xvh, g_xv_h);
    cudaGetSymbolAddress((void**)&wqh, g_wq_h); cudaGetSymbolAddress((void**)&wql, g_wq_l);
    cudaGetSymbolAddress((void**)&wkh, g_wk_h); cudaGetSymbolAddress((void**)&wkl, g_wk_l);
    cudaGetSymbolAddress((void**)&wvh, g_wv_h); cudaGetSymbolAddress((void**)&wvl, g_wv_l);
    cudaGetSymbolAddress((void**)&qh,  g_q_h);
    cudaGetSymbolAddress((void**)&kh,  g_k_h);  cudaGetSymbolAddress((void**)&kl,  g_k_l);
    cudaGetSymbolAddress((void**)&vth, g_vt_h); cudaGetSymbolAddress((void**)&vtl, g_vt_l);
    cudaGetSymbolAddress((void**)&ath, g_a_h);
    cudaGetSymbolAddress((void**)&vf,  g_v);
    cudaGetSymbolAddress((void**)&part, g_part);
    cudaGetSymbolAddress((void**)&rsum, g_rsum);

    cudaFuncSetAttribute(gemm_f16, cudaFuncAttributeMaxDynamicSharedMemorySize, SMEM_REQ);

    const long long MM = 1024LL * 1024;

    // 1) inputs -> f16 (hi only); weights -> hi/lo split (x32)
    {
        ConvArgs in;
        in.x[0] = query; in.h[0] = xqh;
        in.x[1] = key;   in.h[1] = xkh;
        in.x[2] = value; in.h[2] = xvh;
        convert3_kernel<<<dim3(16384, 3), 256>>>(in);
        SplitArgs w;
        w.x[0] = wq; w.h[0] = wqh; w.l[0] = wql;
        w.x[1] = wk; w.h[1] = wkh; w.l[1] = wkl;
        w.x[2] = wv; w.h[2] = wvh; w.l[2] = wvl;
        split3_kernel<<<dim3(1024, 3), 256>>>(w, 32.0f);
    }

    // 2) merged projections (2-term: xh*wh + xh*wl): f = acc/32 + bias
    //    q -> hi-only batch-major (mode 5); k -> hi/lo batch-major (mode 4);
    //    v -> fp32 row-major (mode 0).
    {
        GArgs a = {};
        a.Ah[0] = xqh; a.Bh[0] = wqh; a.Bl[0] = wql;
        a.Ah[1] = xkh; a.Bh[1] = wkh; a.Bl[1] = wkl;
        a.Ah[2] = xvh; a.Bh[2] = wvh; a.Bl[2] = wvl;
        a.Ch[0] = qh;
        a.Ch[1] = kh; a.Cl[1] = kl;
        a.Cf[2] = vf;
        a.bias[0] = bias; a.bias[1] = bias + 1024; a.bias[2] = bias + 2048;
        a.mode[0] = 5; a.mode[1] = 4; a.mode[2] = 0;
        a.lda = 1024; a.ldb = 1024; a.ldc = 1024;
        a.sA = 0; a.sB = 0; a.sC = 0;
        a.K = 1024; a.batched = 0; a.ascale = 1.0f / 32.0f;
        gemm_f16<<<dim3(8, 128, 3), 256, SMEM_REQ>>>(a);
    }

    // 3) V transpose + split
    transpose_split_kernel<<<dim3(16, 16, 16), 256>>>(vf, vth, vtl);

    // 4) scores (2-term: qh*kh + qh*kl) + fused exp/partial-rowsum
    {
        GArgs a = {};
        a.Ah[0] = qh; a.Bh[0] = kh; a.Bl[0] = kl;
        a.Ch[0] = ath;
        a.mode[0] = 2;
        a.lda = 1024; a.ldb = 1024; a.ldc = 1024;
        a.sA = 1LL << 20; a.sB = 1LL << 20; a.sC = MM;
        a.K = 1024; a.batched = 1; a.ascale = 1.0f / 32.0f;
        a.part = part;
        gemm_f16<<<dim3(8, 8, 16), 256, SMEM_REQ>>>(a);
    }

    // 5) row-sum reciprocal
    rowsum_kernel<<<64, 256>>>(part, rsum);

    // 6) out = (e @ vt^T) * rsum[row]  (2-term: ah*vh + ah*vl)
    {
        GArgs a = {};
        a.Ah[0] = ath; a.Bh[0] = vth; a.Bl[0] = vtl;
        a.Cf[0] = out;
        a.mode[0] = 3;
        a.lda = 1024; a.ldb = 1024; a.ldc = 16384;
        a.sA = MM; a.sB = MM; a.sC = 1024;
        a.K = 1024; a.batched = 1; a.ascale = 1.0f;
        a.rsum = rsum;
        gemm_f16<<<dim3(8, 8, 16), 256, SMEM_REQ>>>(a);
    }
}

// round 12
// speedup vs baseline: 2.3863x; 1.4274x over previous
#include <cuda_runtime.h>
#include <cuda_fp16.h>
#include <cstdint>

// ---------------------------------------------------------------------------
// CLIPDecoder_83786222011049 — single-head MHA forward.
// Round 12: pure-fp16 projections + AV (1-term); scores 2-term (k hi+lo).
// 6 GEMM-units total. Calibrated error model predicts rel_err ~5.8e-4.
// q/k batch-major; SW64 swizzle; 3-stage cp.async; ldmatrix; fused softmax.
// ---------------------------------------------------------------------------

static constexpr int BM = 128, BN = 128, BK = 32;
static constexpr int TILE_B = 128 * 64;             // 8192 B per half-tile
static constexpr int SMEM1 = 3 * 2 * TILE_B;        // 49152 (Ah, Bh)
static constexpr int SMEM2 = 3 * 3 * TILE_B;        // 73728 (Ah, Bh, Bl)

// ---------------------------------------------------------------------------
// Scratch (device globals).
// ---------------------------------------------------------------------------
#define BIGH (size_t)(16384) * 1024
#define BATH (size_t)(16) * 1024 * 1024
__device__ __align__(256) __half g_xq_h[BIGH];
__device__ __align__(256) __half g_xk_h[BIGH];
__device__ __align__(256) __half g_xv_h[BIGH];
__device__ __align__(256) __half g_wq_h[1024*1024];
__device__ __align__(256) __half g_wk_h[1024*1024];
__device__ __align__(256) __half g_wv_h[1024*1024];
__device__ __align__(256) __half g_q_h[BIGH];                     // [nb][l][e]
__device__ __align__(256) __half g_k_h[BIGH], g_k_l[BIGH];        // [nb][l][e]
__device__ __align__(256) float  g_v[BIGH];
__device__ __align__(256) __half g_vt_h[BATH];                    // [nb][f][s]
__device__ __align__(256) __half g_a_h[BATH];                     // [nb][l][s]
__device__ __align__(256) float  g_part[(size_t)16 * 1024 * 8];
__device__ __align__(256) float  g_rsum[(size_t)16 * 1024];

// ---------------------------------------------------------------------------
// PTX helpers
// ---------------------------------------------------------------------------
__device__ __forceinline__ void cp16(uint32_t sdst, const void* gsrc) {
    asm volatile("cp.async.cg.shared.global [%0], [%1], 16;\n"
                 :: "r"(sdst), "l"(gsrc));
}
__device__ __forceinline__ void cp_commit() {
    asm volatile("cp.async.commit_group;\n" ::: "memory");
}
template <int N> __device__ __forceinline__ void cp_wait() {
    asm volatile("cp.async.wait_group %0;\n" :: "n"(N) : "memory");
}
__device__ __forceinline__ void ldsm4(uint32_t* r, uint32_t addr) {
    asm volatile("ldmatrix.sync.aligned.m8n8.x4.shared.b16 {%0,%1,%2,%3}, [%4];"
                 : "=r"(r[0]), "=r"(r[1]), "=r"(r[2]), "=r"(r[3]) : "r"(addr));
}
__device__ __forceinline__ void mma16(float* d, const uint32_t* a, const uint32_t* b) {
    asm volatile(
        "mma.sync.aligned.m16n8k16.row.col.f32.f16.f16.f32 "
        "{%0,%1,%2,%3},{%4,%5,%6,%7},{%8,%9},{%0,%1,%2,%3};\n"
        : "+f"(d[0]), "+f"(d[1]), "+f"(d[2]), "+f"(d[3])
        : "r"(a[0]), "r"(a[1]), "r"(a[2]), "r"(a[3]), "r"(b[0]), "r"(b[1]));
}
__device__ __forceinline__ uint32_t pk2h(float a, float b) {
    __half2 t = __floats2half2_rn(a, b);
    return *reinterpret_cast<uint32_t*>(&t);
}

extern __shared__ char dynsm[];

// ---------------------------------------------------------------------------
// GEMM (NT). TERMS=1: D = Ah*Bh.  TERMS=2: D = Ah*Bh + Ah*Bl.
// batched==0: blockIdx.z selects operand set. batched==1: z = batch index.
// mode: 0 fp32 out (+bias)
//       2 exp epilogue: hi out + row-sum partials
//       3 fp32 out * rsum[row]
//       4 hi/lo split out, batch-transposed [nb][l][e] (+bias)
//       5 hi-only out,  batch-transposed [nb][l][e] (+bias)
// SMEM: 64B rows, SW64 swizzle (byte16-col ^ ((row&6)<<3)).
// ---------------------------------------------------------------------------
struct GArgs {
    const __half* Ah[3];
    const __half* Bh[3]; const __half* Bl[3];
    float* Cf[3]; __half* Ch[3]; __half* Cl[3];
    const float* bias[3];
    int mode[3];
    long long lda, ldb, ldc;
    long long sA, sB, sC;
    int K, batched;
    float ascale;
    float* part;
    const float* rsum;
};

template <int TERMS>
__global__ __launch_bounds__(256, 2) void gemm_f16(GArgs p)
{
    constexpr int AH_O = 0, BH_O = TILE_B, BL_O = 2 * TILE_B;
    constexpr int STAGE_B = (1 + TERMS) * TILE_B;

    const uint32_t sbase = (uint32_t)__cvta_generic_to_shared(dynsm);
    const int tid = threadIdx.x, lane = tid & 31, warp = tid >> 5;
    const int wm = warp & 1, wn = warp >> 1;      // 2(m) x 4(n) warps
    const int q = lane & 3, g = lane >> 2;

    const int zi = p.batched ? 0 : (int)blockIdx.z;
    const long long bz = p.batched ? (long long)blockIdx.z : 0;
    const int mode = p.mode[zi];

    const long long m0 = (long long)blockIdx.y * BM;
    const long long n0 = (long long)blockIdx.x * BN;

    const char* Ahb = (const char*)(p.Ah[zi] + bz * p.sA + m0 * p.lda);
    const char* Bhb = (const char*)(p.Bh[zi] + bz * p.sB + n0 * p.ldb);
    const char* Blb = (const char*)(p.Bl[zi] + bz * p.sB + n0 * p.ldb);

    // ldmatrix lane addressing (SW64)
    const int a_row = wm * 64 + (lane & 15);
    const uint32_t a_base = (uint32_t)(a_row * 64);
    const uint32_t a_cs = (uint32_t)(((lane >> 4) << 4) ^ ((a_row & 6) << 3));
    const int b_row = wn * 32 + ((lane >> 4) & 1) * 8 + (lane & 7);
    const uint32_t b_base = (uint32_t)(b_row * 64);
    const uint32_t b_cs = (uint32_t)((((lane >> 3) & 1) << 4) ^ ((b_row & 6) << 3));

    float acc[4][4][4];
    #pragma unroll
    for (int i = 0; i < 4; ++i)
        #pragma unroll
        for (int j = 0; j < 4; ++j)
            #pragma unroll
            for (int r = 0; r < 4; ++r) acc[i][j][r] = 0.0f;

    const int KT = p.K / BK;
    const long long lda2 = p.lda * 2, ldb2 = p.ldb * 2;

    const int srow = tid >> 2;
    const uint32_t sc16 = (uint32_t)(((tid & 3) << 4) ^ ((srow & 6) << 3));

    auto load_tile = [&](int kt) {
        const uint32_t sb = sbase + (kt % 3) * STAGE_B;
        const long long kb = (long long)kt * (BK * 2);
        #pragma unroll
        for (int pp = 0; pp < 2; ++pp) {
            const int r = srow + pp * 64;
            const uint32_t d = (uint32_t)(r * 64) + sc16;
            const long long ga = (long long)r * lda2 + kb + ((tid & 3) << 4);
            const long long gb = (long long)r * ldb2 + kb + ((tid & 3) << 4);
            cp16(sb + AH_O + d, Ahb + ga);
            cp16(sb + BH_O + d, Bhb + gb);
            if (TERMS == 2) cp16(sb + BL_O + d, Blb + gb);
        }
        cp_commit();
    };

    auto compute = [&](int kt) {
        const uint32_t sb = sbase + (kt % 3) * STAGE_B;
        #pragma unroll
        for (int kk = 0; kk < 2; ++kk) {
            const uint32_t ka = kk * 32;
            const uint32_t aoff = a_base + (ka ^ a_cs);
            const uint32_t boff = b_base + (ka ^ b_cs);
            uint32_t ah[4][4];
            #pragma unroll
            for (int i = 0; i < 4; ++i)
                ldsm4(ah[i], sb + AH_O + aoff + i * 1024);
            uint32_t bh[4][2], bl[4][2];
            #pragma unroll
            for (int jp = 0; jp < 2; ++jp) {
                uint32_t rb[4];
                ldsm4(rb, sb + BH_O + boff + jp * 1024);
                bh[2*jp][0] = rb[0]; bh[2*jp][1] = rb[1];
                bh[2*jp+1][0] = rb[2]; bh[2*jp+1][1] = rb[3];
                if (TERMS == 2) {
                    ldsm4(rb, sb + BL_O + boff + jp * 1024);
                    bl[2*jp][0] = rb[0]; bl[2*jp][1] = rb[1];
                    bl[2*jp+1][0] = rb[2]; bl[2*jp+1][1] = rb[3];
                }
            }
            #pragma unroll
            for (int i = 0; i < 4; ++i)
                #pragma unroll
                for (int j = 0; j < 4; ++j) {
                    mma16(acc[i][j], ah[i], bh[j]);
                    if (TERMS == 2) mma16(acc[i][j], ah[i], bl[j]);
                }
        }
    };

    // 3-stage pipeline, prefetch distance 2.
    load_tile(0);
    load_tile(1);
    for (int kt = 0; kt < KT; ++kt) {
        cp_wait<1>();
        __syncthreads();
        if (kt + 2 < KT) load_tile(kt + 2);
        else             cp_commit();
        compute(kt);
    }

    // ---------------- epilogues ----------------
    if (mode == 2) {
        __syncthreads();
        float (*srows)[4] = reinterpret_cast<float(*)[4]>(dynsm);
        __half* Ch = p.Ch[zi];
        #pragma unroll
        for (int i = 0; i < 4; ++i) {
            float p0 = 0.0f, p1 = 0.0f;
            const long long r0 = m0 + wm * 64 + i * 16 + g;
            #pragma unroll
            for (int j = 0; j < 4; ++j) {
                float e0 = __expf(acc[i][j][0] * p.ascale);
                float e1 = __expf(acc[i][j][1] * p.ascale);
                float e2 = __expf(acc[i][j][2] * p.ascale);
                float e3 = __expf(acc[i][j][3] * p.ascale);
                p0 += e0 + e1;  p1 += e2 + e3;
                const long long c0 = n0 + wn * 32 + j * 8 + 2 * q;
                *(uint32_t*)(Ch + bz * p.sC + r0 * p.ldc + c0)       = pk2h(e0, e1);
                *(uint32_t*)(Ch + bz * p.sC + (r0 + 8) * p.ldc + c0) = pk2h(e2, e3);
            }
            p0 += __shfl_xor_sync(0xFFFFFFFFu, p0, 1);
            p0 += __shfl_xor_sync(0xFFFFFFFFu, p0, 2);
            p1 += __shfl_xor_sync(0xFFFFFFFFu, p1, 1);
            p1 += __shfl_xor_sync(0xFFFFFFFFu, p1, 2);
            if (q == 0) {
                srows[wm * 64 + i * 16 + g][wn]     = p0;
                srows[wm * 64 + i * 16 + g + 8][wn] = p1;
            }
        }
        __syncthreads();
        if (tid < 128) {
            float s = srows[tid][0] + srows[tid][1] + srows[tid][2] + srows[tid][3];
            p.part[((bz << 10) + m0 + tid) * 8 + blockIdx.x] = s;
        }
        return;
    }

    if (mode == 3) {
        float* Cf = p.Cf[zi];
        #pragma unroll
        for (int i = 0; i < 4; ++i) {
            const long long r0 = m0 + wm * 64 + i * 16 + g;
            const float rs0 = p.rsum[(bz << 10) + r0];
            const float rs1 = p.rsum[(bz << 10) + r0 + 8];
            #pragma unroll
            for (int j = 0; j < 4; ++j) {
                const long long c0 = n0 + wn * 32 + j * 8 + 2 * q;
                *(float2*)(Cf + bz * p.sC + r0 * p.ldc + c0) =
                    make_float2(acc[i][j][0] * rs0, acc[i][j][1] * rs0);
                *(float2*)(Cf + bz * p.sC + (r0 + 8) * p.ldc + c0) =
                    make_float2(acc[i][j][2] * rs1, acc[i][j][3] * rs1);
            }
        }
        return;
    }

    // modes 0 / 4 / 5: f = acc*ascale + bias
    const float* bias = p.bias[zi];
    #pragma unroll
    for (int i = 0; i < 4; ++i) {
        const long long r0 = m0 + wm * 64 + i * 16 + g;
        const long long r1 = r0 + 8;
        // batch-transposed addresses (modes 4/5): [nb][l][e]
        const long long t0 = ((r0 & 15) << 20) + ((r0 >> 4) << 10);
        const long long t1 = ((r1 & 15) << 20) + ((r1 >> 4) << 10);
        #pragma unroll
        for (int j = 0; j < 4; ++j) {
            const long long c0 = n0 + wn * 32 + j * 8 + 2 * q;
            const float b0 = bias ? bias[c0]     : 0.0f;
            const float b1 = bias ? bias[c0 + 1] : 0.0f;
            float x0 = acc[i][j][0] * p.ascale + b0;
            float x1 = acc[i][j][1] * p.ascale + b1;
            float x2 = acc[i][j][2] * p.ascale + b0;
            float x3 = acc[i][j][3] * p.ascale + b1;
            if (mode == 0) {
                float* Cf = p.Cf[zi];
                *(float2*)(Cf + r0 * p.ldc + c0) = make_float2(x0, x1);
                *(float2*)(Cf + r1 * p.ldc + c0) = make_float2(x2, x3);
            } else {
                __half* Ch = p.Ch[zi];
                *(uint32_t*)(Ch + t0 + c0) = pk2h(x0, x1);
                *(uint32_t*)(Ch + t1 + c0) = pk2h(x2, x3);
                if (mode == 4) {
                    __half* Cl = p.Cl[zi];
                    __half h0 = __float2half_rn(x0), h1 = __float2half_rn(x1);
                    __half h2 = __float2half_rn(x2), h3 = __float2half_rn(x3);
                    float l0 = x0 - __half2float(h0), l1 = x1 - __half2float(h1);
                    float l2 = x2 - __half2float(h2), l3 = x3 - __half2float(h3);
                    *(uint32_t*)(Cl + t0 + c0) = pk2h(l0, l1);
                    *(uint32_t*)(Cl + t1 + c0) = pk2h(l2, l3);
                }
            }
        }
    }
}

// ---------------------------------------------------------------------------
// fp32 -> f16 (hi only), 3 arrays fused via blockIdx.y.
// ---------------------------------------------------------------------------
struct ConvArgs {
    const float* x[3];
    __half* h[3];
};

__global__ __launch_bounds__(256) void convert3_kernel(ConvArgs args)
{
    const int a = blockIdx.y;
    const long long i = (long long)blockIdx.x * 256 + threadIdx.x;
    float4 v = ((const float4*)args.x[a])[i];
    ((uint2*)args.h[a])[i] = make_uint2(pk2h(v.x, v.y), pk2h(v.z, v.w));
}

// ---------------------------------------------------------------------------
// Transpose + convert V:  v[(s*16+nb)*1024 + f] (fp32) -> vt_h[nb][f][s]
// ---------------------------------------------------------------------------
__global__ __launch_bounds__(256) void transpose_conv_kernel(
    const float* __restrict__ v, __half* __restrict__ vth)
{
    __shared__ float t[64][65];
    const int nb = blockIdx.z;
    const int s0 = blockIdx.x * 64, f0 = blockIdx.y * 64;
    const int c = threadIdx.x & 63, r0 = threadIdx.x >> 6;

    #pragma unroll
    for (int rr = r0; rr < 64; rr += 4)
        t[rr][c] = v[(long long)((s0 + rr) * 16 + nb) * 1024 + f0 + c];
    __syncthreads();

    __half* oh = vth + (size_t)nb * 1024 * 1024;
    #pragma unroll
    for (int rr = r0; rr < 64; rr += 4) {
        size_t idx = (size_t)(f0 + rr) * 1024 + s0 + c;
        oh[idx] = __float2half_rn(t[c][rr]);
    }
}

// ---------------------------------------------------------------------------
// rsum[row] = 1 / sum_{cb<8} part[row*8+cb]
// ---------------------------------------------------------------------------
__global__ __launch_bounds__(256) void rowsum_kernel(
    const float* __restrict__ part, float* __restrict__ rsum)
{
    const int row = blockIdx.x * 256 + threadIdx.x;
    const float4 a = ((const float4*)part)[row * 2];
    const float4 b = ((const float4*)part)[row * 2 + 1];
    rsum[row] = 1.0f / (((a.x + a.y) + (a.z + a.w)) + ((b.x + b.y) + (b.z + b.w)));
}

// ---------------------------------------------------------------------------
// Launch
// ---------------------------------------------------------------------------
extern "C" void kernel_launch(void* const* d_in, const int* in_sizes, int n_in,
                              void* d_out, int out_size)
{
    const float* query = (const float*)d_in[0];
    const float* key   = (const float*)d_in[1];
    const float* value = (const float*)d_in[2];
    const float* wq    = (const float*)d_in[3];
    const float* wk    = (const float*)d_in[4];
    const float* wv    = (const float*)d_in[5];
    const float* bias  = (const float*)d_in[6];
    float* out = (float*)d_out;

    __half *xqh,*xkh,*xvh, *wqh,*wkh,*wvh;
    __half *qh,*kh,*kl,*vth,*ath;
    float *vf, *part, *rsum;
    cudaGetSymbolAddress((void**)&xqh, g_xq_h);
    cudaGetSymbolAddress((void**)&xkh, g_xk_h);
    cudaGetSymbolAddress((void**)&xvh, g_xv_h);
    cudaGetSymbolAddress((void**)&wqh, g_wq_h);
    cudaGetSymbolAddress((void**)&wkh, g_wk_h);
    cudaGetSymbolAddress((void**)&wvh, g_wv_h);
    cudaGetSymbolAddress((void**)&qh,  g_q_h);
    cudaGetSymbolAddress((void**)&kh,  g_k_h);
    cudaGetSymbolAddress((void**)&kl,  g_k_l);
    cudaGetSymbolAddress((void**)&vth, g_vt_h);
    cudaGetSymbolAddress((void**)&ath, g_a_h);
    cudaGetSymbolAddress((void**)&vf,  g_v);
    cudaGetSymbolAddress((void**)&part, g_part);
    cudaGetSymbolAddress((void**)&rsum, g_rsum);

    cudaFuncSetAttribute(gemm_f16<1>, cudaFuncAttributeMaxDynamicSharedMemorySize, SMEM1);
    cudaFuncSetAttribute(gemm_f16<2>, cudaFuncAttributeMaxDynamicSharedMemorySize, SMEM2);

    const long long MM = 1024LL * 1024;

    // 1) inputs and weights -> f16 (hi only)
    {
        ConvArgs in;
        in.x[0] = query; in.h[0] = xqh;
        in.x[1] = key;   in.h[1] = xkh;
        in.x[2] = value; in.h[2] = xvh;
        convert3_kernel<<<dim3(16384, 3), 256>>>(in);
        ConvArgs w;
        w.x[0] = wq; w.h[0] = wqh;
        w.x[1] = wk; w.h[1] = wkh;
        w.x[2] = wv; w.h[2] = wvh;
        convert3_kernel<<<dim3(1024, 3), 256>>>(w);
    }

    // 2) merged projections (1-term): f = acc + bias
    //    q -> hi-only batch-major (mode 5); k -> hi/lo batch-major (mode 4);
    //    v -> fp32 row-major (mode 0).
    {
        GArgs a = {};
        a.Ah[0] = xqh; a.Bh[0] = wqh;
        a.Ah[1] = xkh; a.Bh[1] = wkh;
        a.Ah[2] = xvh; a.Bh[2] = wvh;
        a.Ch[0] = qh;
        a.Ch[1] = kh; a.Cl[1] = kl;
        a.Cf[2] = vf;
        a.bias[0] = bias; a.bias[1] = bias + 1024; a.bias[2] = bias + 2048;
        a.mode[0] = 5; a.mode[1] = 4; a.mode[2] = 0;
        a.lda = 1024; a.ldb = 1024; a.ldc = 1024;
        a.sA = 0; a.sB = 0; a.sC = 0;
        a.K = 1024; a.batched = 0; a.ascale = 1.0f;
        gemm_f16<1><<<dim3(8, 128, 3), 256, SMEM1>>>(a);
    }

    // 3) V transpose + convert
    transpose_conv_kernel<<<dim3(16, 16, 16), 256>>>(vf, vth);

    // 4) scores (2-term: qh*kh + qh*kl) + fused exp/partial-rowsum
    {
        GArgs a = {};
        a.Ah[0] = qh; a.Bh[0] = kh; a.Bl[0] = kl;
        a.Ch[0] = ath;
        a.mode[0] = 2;
        a.lda = 1024; a.ldb = 1024; a.ldc = 1024;
        a.sA = 1LL << 20; a.sB = 1LL << 20; a.sC = MM;
        a.K = 1024; a.batched = 1; a.ascale = 1.0f / 32.0f;
        a.part = part;
        gemm_f16<2><<<dim3(8, 8, 16), 256, SMEM2>>>(a);
    }

    // 5) row-sum reciprocal
    rowsum_kernel<<<64, 256>>>(part, rsum);

    // 6) out = (e @ vt^T) * rsum[row]  (1-term: ah*vh)
    {
        GArgs a = {};
        a.Ah[0] = ath; a.Bh[0] = vth;
        a.Cf[0] = out;
        a.mode[0] = 3;
        a.lda = 1024; a.ldb = 1024; a.ldc = 16384;
        a.sA = MM; a.sB = MM; a.sC = 1024;
        a.K = 1024; a.batched = 1; a.ascale = 1.0f;
        a.rsum = rsum;
        gemm_f16<1><<<dim3(8, 8, 16), 256, SMEM1>>>(a);
    }
}

// round 13
// speedup vs baseline: 2.7385x; 1.1476x over previous
#include <cuda_runtime.h>
#include <cuda_fp16.h>
#include <cstdint>

// ---------------------------------------------------------------------------
// CLIPDecoder_83786222011049 — single-head MHA forward.
// Round 13: ALL GEMMs pure fp16 (1-term). 5 GEMM-units. Calibrated error
// model predicts rel_err ~6.1e-4 (quadrature). q/k batch-major; SW64
// swizzle; 3-stage cp.async; ldmatrix; fused exp/rowsum softmax.
// ---------------------------------------------------------------------------

static constexpr int BM = 128, BN = 128, BK = 32;
static constexpr int TILE_B = 128 * 64;             // 8192 B per tile
static constexpr int STAGE_B = 2 * TILE_B;          // Ah, Bh
static constexpr int SMEM_REQ = 3 * STAGE_B;        // 49152

// ---------------------------------------------------------------------------
// Scratch (device globals).
// ---------------------------------------------------------------------------
#define BIGH (size_t)(16384) * 1024
#define BATH (size_t)(16) * 1024 * 1024
__device__ __align__(256) __half g_xq_h[BIGH];
__device__ __align__(256) __half g_xk_h[BIGH];
__device__ __align__(256) __half g_xv_h[BIGH];
__device__ __align__(256) __half g_wq_h[1024*1024];
__device__ __align__(256) __half g_wk_h[1024*1024];
__device__ __align__(256) __half g_wv_h[1024*1024];
__device__ __align__(256) __half g_q_h[BIGH];                     // [nb][l][e]
__device__ __align__(256) __half g_k_h[BIGH];                     // [nb][l][e]
__device__ __align__(256) float  g_v[BIGH];
__device__ __align__(256) __half g_vt_h[BATH];                    // [nb][f][s]
__device__ __align__(256) __half g_a_h[BATH];                     // [nb][l][s]
__device__ __align__(256) float  g_part[(size_t)16 * 1024 * 8];
__device__ __align__(256) float  g_rsum[(size_t)16 * 1024];

// ---------------------------------------------------------------------------
// PTX helpers
// ---------------------------------------------------------------------------
__device__ __forceinline__ void cp16(uint32_t sdst, const void* gsrc) {
    asm volatile("cp.async.cg.shared.global [%0], [%1], 16;\n"
                 :: "r"(sdst), "l"(gsrc));
}
__device__ __forceinline__ void cp_commit() {
    asm volatile("cp.async.commit_group;\n" ::: "memory");
}
template <int N> __device__ __forceinline__ void cp_wait() {
    asm volatile("cp.async.wait_group %0;\n" :: "n"(N) : "memory");
}
__device__ __forceinline__ void ldsm4(uint32_t* r, uint32_t addr) {
    asm volatile("ldmatrix.sync.aligned.m8n8.x4.shared.b16 {%0,%1,%2,%3}, [%4];"
                 : "=r"(r[0]), "=r"(r[1]), "=r"(r[2]), "=r"(r[3]) : "r"(addr));
}
__device__ __forceinline__ void mma16(float* d, const uint32_t* a, const uint32_t* b) {
    asm volatile(
        "mma.sync.aligned.m16n8k16.row.col.f32.f16.f16.f32 "
        "{%0,%1,%2,%3},{%4,%5,%6,%7},{%8,%9},{%0,%1,%2,%3};\n"
        : "+f"(d[0]), "+f"(d[1]), "+f"(d[2]), "+f"(d[3])
        : "r"(a[0]), "r"(a[1]), "r"(a[2]), "r"(a[3]), "r"(b[0]), "r"(b[1]));
}
__device__ __forceinline__ uint32_t pk2h(float a, float b) {
    __half2 t = __floats2half2_rn(a, b);
    return *reinterpret_cast<uint32_t*>(&t);
}

extern __shared__ char dynsm[];

// ---------------------------------------------------------------------------
// GEMM (NT), 1-term fp16: D = Ah*Bh.
// batched==0: blockIdx.z selects operand set. batched==1: z = batch index.
// mode: 0 fp32 out (+bias)
//       2 exp epilogue: hi out + row-sum partials
//       3 fp32 out * rsum[row]
//       5 hi-only out, batch-transposed [nb][l][e] (+bias)
// SMEM: 64B rows, SW64 swizzle (byte16-col ^ ((row&6)<<3)).
// ---------------------------------------------------------------------------
struct GArgs {
    const __half* Ah[3];
    const __half* Bh[3];
    float* Cf[3]; __half* Ch[3];
    const float* bias[3];
    int mode[3];
    long long lda, ldb, ldc;
    long long sA, sB, sC;
    int K, batched;
    float ascale;
    float* part;
    const float* rsum;
};

__global__ __launch_bounds__(256, 2) void gemm_f16(GArgs p)
{
    constexpr int AH_O = 0, BH_O = TILE_B;

    const uint32_t sbase = (uint32_t)__cvta_generic_to_shared(dynsm);
    const int tid = threadIdx.x, lane = tid & 31, warp = tid >> 5;
    const int wm = warp & 1, wn = warp >> 1;      // 2(m) x 4(n) warps
    const int q = lane & 3, g = lane >> 2;

    const int zi = p.batched ? 0 : (int)blockIdx.z;
    const long long bz = p.batched ? (long long)blockIdx.z : 0;
    const int mode = p.mode[zi];

    const long long m0 = (long long)blockIdx.y * BM;
    const long long n0 = (long long)blockIdx.x * BN;

    const char* Ahb = (const char*)(p.Ah[zi] + bz * p.sA + m0 * p.lda);
    const char* Bhb = (const char*)(p.Bh[zi] + bz * p.sB + n0 * p.ldb);

    // ldmatrix lane addressing (SW64)
    const int a_row = wm * 64 + (lane & 15);
    const uint32_t a_base = (uint32_t)(a_row * 64);
    const uint32_t a_cs = (uint32_t)(((lane >> 4) << 4) ^ ((a_row & 6) << 3));
    const int b_row = wn * 32 + ((lane >> 4) & 1) * 8 + (lane & 7);
    const uint32_t b_base = (uint32_t)(b_row * 64);
    const uint32_t b_cs = (uint32_t)((((lane >> 3) & 1) << 4) ^ ((b_row & 6) << 3));

    float acc[4][4][4];
    #pragma unroll
    for (int i = 0; i < 4; ++i)
        #pragma unroll
        for (int j = 0; j < 4; ++j)
            #pragma unroll
            for (int r = 0; r < 4; ++r) acc[i][j][r] = 0.0f;

    const int KT = p.K / BK;
    const long long lda2 = p.lda * 2, ldb2 = p.ldb * 2;

    const int srow = tid >> 2;
    const uint32_t sc16 = (uint32_t)(((tid & 3) << 4) ^ ((srow & 6) << 3));

    auto load_tile = [&](int kt) {
        const uint32_t sb = sbase + (kt % 3) * STAGE_B;
        const long long kb = (long long)kt * (BK * 2);
        #pragma unroll
        for (int pp = 0; pp < 2; ++pp) {
            const int r = srow + pp * 64;
            const uint32_t d = (uint32_t)(r * 64) + sc16;
            const long long ga = (long long)r * lda2 + kb + ((tid & 3) << 4);
            const long long gb = (long long)r * ldb2 + kb + ((tid & 3) << 4);
            cp16(sb + AH_O + d, Ahb + ga);
            cp16(sb + BH_O + d, Bhb + gb);
        }
        cp_commit();
    };

    auto compute = [&](int kt) {
        const uint32_t sb = sbase + (kt % 3) * STAGE_B;
        #pragma unroll
        for (int kk = 0; kk < 2; ++kk) {
            const uint32_t ka = kk * 32;
            const uint32_t aoff = a_base + (ka ^ a_cs);
            const uint32_t boff = b_base + (ka ^ b_cs);
            uint32_t ah[4][4];
            #pragma unroll
            for (int i = 0; i < 4; ++i)
                ldsm4(ah[i], sb + AH_O + aoff + i * 1024);
            uint32_t bh[4][2];
            #pragma unroll
            for (int jp = 0; jp < 2; ++jp) {
                uint32_t rb[4];
                ldsm4(rb, sb + BH_O + boff + jp * 1024);
                bh[2*jp][0] = rb[0]; bh[2*jp][1] = rb[1];
                bh[2*jp+1][0] = rb[2]; bh[2*jp+1][1] = rb[3];
            }
            #pragma unroll
            for (int i = 0; i < 4; ++i)
                #pragma unroll
                for (int j = 0; j < 4; ++j)
                    mma16(acc[i][j], ah[i], bh[j]);
        }
    };

    // 3-stage pipeline, prefetch distance 2.
    load_tile(0);
    load_tile(1);
    for (int kt = 0; kt < KT; ++kt) {
        cp_wait<1>();
        __syncthreads();
        if (kt + 2 < KT) load_tile(kt + 2);
        else             cp_commit();
        compute(kt);
    }

    // ---------------- epilogues ----------------
    if (mode == 2) {
        __syncthreads();
        float (*srows)[4] = reinterpret_cast<float(*)[4]>(dynsm);
        __half* Ch = p.Ch[zi];
        #pragma unroll
        for (int i = 0; i < 4; ++i) {
            float p0 = 0.0f, p1 = 0.0f;
            const long long r0 = m0 + wm * 64 + i * 16 + g;
            #pragma unroll
            for (int j = 0; j < 4; ++j) {
                float e0 = __expf(acc[i][j][0] * p.ascale);
                float e1 = __expf(acc[i][j][1] * p.ascale);
                float e2 = __expf(acc[i][j][2] * p.ascale);
                float e3 = __expf(acc[i][j][3] * p.ascale);
                p0 += e0 + e1;  p1 += e2 + e3;
                const long long c0 = n0 + wn * 32 + j * 8 + 2 * q;
                *(uint32_t*)(Ch + bz * p.sC + r0 * p.ldc + c0)       = pk2h(e0, e1);
                *(uint32_t*)(Ch + bz * p.sC + (r0 + 8) * p.ldc + c0) = pk2h(e2, e3);
            }
            p0 += __shfl_xor_sync(0xFFFFFFFFu, p0, 1);
            p0 += __shfl_xor_sync(0xFFFFFFFFu, p0, 2);
            p1 += __shfl_xor_sync(0xFFFFFFFFu, p1, 1);
            p1 += __shfl_xor_sync(0xFFFFFFFFu, p1, 2);
            if (q == 0) {
                srows[wm * 64 + i * 16 + g][wn]     = p0;
                srows[wm * 64 + i * 16 + g + 8][wn] = p1;
            }
        }
        __syncthreads();
        if (tid < 128) {
            float s = srows[tid][0] + srows[tid][1] + srows[tid][2] + srows[tid][3];
            p.part[((bz << 10) + m0 + tid) * 8 + blockIdx.x] = s;
        }
        return;
    }

    if (mode == 3) {
        float* Cf = p.Cf[zi];
        #pragma unroll
        for (int i = 0; i < 4; ++i) {
            const long long r0 = m0 + wm * 64 + i * 16 + g;
            const float rs0 = p.rsum[(bz << 10) + r0];
            const float rs1 = p.rsum[(bz << 10) + r0 + 8];
            #pragma unroll
            for (int j = 0; j < 4; ++j) {
                const long long c0 = n0 + wn * 32 + j * 8 + 2 * q;
                *(float2*)(Cf + bz * p.sC + r0 * p.ldc + c0) =
                    make_float2(acc[i][j][0] * rs0, acc[i][j][1] * rs0);
                *(float2*)(Cf + bz * p.sC + (r0 + 8) * p.ldc + c0) =
                    make_float2(acc[i][j][2] * rs1, acc[i][j][3] * rs1);
            }
        }
        return;
    }

    // modes 0 / 5: f = acc*ascale + bias
    const float* bias = p.bias[zi];
    #pragma unroll
    for (int i = 0; i < 4; ++i) {
        const long long r0 = m0 + wm * 64 + i * 16 + g;
        const long long r1 = r0 + 8;
        // batch-transposed addresses (mode 5): [nb][l][e]
        const long long t0 = ((r0 & 15) << 20) + ((r0 >> 4) << 10);
        const long long t1 = ((r1 & 15) << 20) + ((r1 >> 4) << 10);
        #pragma unroll
        for (int j = 0; j < 4; ++j) {
            const long long c0 = n0 + wn * 32 + j * 8 + 2 * q;
            const float b0 = bias ? bias[c0]     : 0.0f;
            const float b1 = bias ? bias[c0 + 1] : 0.0f;
            float x0 = acc[i][j][0] * p.ascale + b0;
            float x1 = acc[i][j][1] * p.ascale + b1;
            float x2 = acc[i][j][2] * p.ascale + b0;
            float x3 = acc[i][j][3] * p.ascale + b1;
            if (mode == 0) {
                float* Cf = p.Cf[zi];
                *(float2*)(Cf + r0 * p.ldc + c0) = make_float2(x0, x1);
                *(float2*)(Cf + r1 * p.ldc + c0) = make_float2(x2, x3);
            } else {
                __half* Ch = p.Ch[zi];
                *(uint32_t*)(Ch + t0 + c0) = pk2h(x0, x1);
                *(uint32_t*)(Ch + t1 + c0) = pk2h(x2, x3);
            }
        }
    }
}

// ---------------------------------------------------------------------------
// fp32 -> f16 (hi only), 3 arrays fused via blockIdx.y.
// ---------------------------------------------------------------------------
struct ConvArgs {
    const float* x[3];
    __half* h[3];
};

__global__ __launch_bounds__(256) void convert3_kernel(ConvArgs args)
{
    const int a = blockIdx.y;
    const long long i = (long long)blockIdx.x * 256 + threadIdx.x;
    float4 v = ((const float4*)args.x[a])[i];
    ((uint2*)args.h[a])[i] = make_uint2(pk2h(v.x, v.y), pk2h(v.z, v.w));
}

// ---------------------------------------------------------------------------
// Transpose + convert V:  v[(s*16+nb)*1024 + f] (fp32) -> vt_h[nb][f][s]
// ---------------------------------------------------------------------------
__global__ __launch_bounds__(256) void transpose_conv_kernel(
    const float* __restrict__ v, __half* __restrict__ vth)
{
    __shared__ float t[64][65];
    const int nb = blockIdx.z;
    const int s0 = blockIdx.x * 64, f0 = blockIdx.y * 64;
    const int c = threadIdx.x & 63, r0 = threadIdx.x >> 6;

    #pragma unroll
    for (int rr = r0; rr < 64; rr += 4)
        t[rr][c] = v[(long long)((s0 + rr) * 16 + nb) * 1024 + f0 + c];
    __syncthreads();

    __half* oh = vth + (size_t)nb * 1024 * 1024;
    #pragma unroll
    for (int rr = r0; rr < 64; rr += 4) {
        size_t idx = (size_t)(f0 + rr) * 1024 + s0 + c;
        oh[idx] = __float2half_rn(t[c][rr]);
    }
}

// ---------------------------------------------------------------------------
// rsum[row] = 1 / sum_{cb<8} part[row*8+cb]
// ---------------------------------------------------------------------------
__global__ __launch_bounds__(256) void rowsum_kernel(
    const float* __restrict__ part, float* __restrict__ rsum)
{
    const int row = blockIdx.x * 256 + threadIdx.x;
    const float4 a = ((const float4*)part)[row * 2];
    const float4 b = ((const float4*)part)[row * 2 + 1];
    rsum[row] = 1.0f / (((a.x + a.y) + (a.z + a.w)) + ((b.x + b.y) + (b.z + b.w)));
}

// ---------------------------------------------------------------------------
// Launch
// ---------------------------------------------------------------------------
extern "C" void kernel_launch(void* const* d_in, const int* in_sizes, int n_in,
                              void* d_out, int out_size)
{
    const float* query = (const float*)d_in[0];
    const float* key   = (const float*)d_in[1];
    const float* value = (const float*)d_in[2];
    const float* wq    = (const float*)d_in[3];
    const float* wk    = (const float*)d_in[4];
    const float* wv    = (const float*)d_in[5];
    const float* bias  = (const float*)d_in[6];
    float* out = (float*)d_out;

    __half *xqh,*xkh,*xvh, *wqh,*wkh,*wvh;
    __half *qh,*kh,*vth,*ath;
    float *vf, *part, *rsum;
    cudaGetSymbolAddress((void**)&xqh, g_xq_h);
    cudaGetSymbolAddress((void**)&xkh, g_xk_h);
    cudaGetSymbolAddress((void**)&xvh, g_xv_h);
    cudaGetSymbolAddress((void**)&wqh, g_wq_h);
    cudaGetSymbolAddress((void**)&wkh, g_wk_h);
    cudaGetSymbolAddress((void**)&wvh, g_wv_h);
    cudaGetSymbolAddress((void**)&qh,  g_q_h);
    cudaGetSymbolAddress((void**)&kh,  g_k_h);
    cudaGetSymbolAddress((void**)&vth, g_vt_h);
    cudaGetSymbolAddress((void**)&ath, g_a_h);
    cudaGetSymbolAddress((void**)&vf,  g_v);
    cudaGetSymbolAddress((void**)&part, g_part);
    cudaGetSymbolAddress((void**)&rsum, g_rsum);

    cudaFuncSetAttribute(gemm_f16, cudaFuncAttributeMaxDynamicSharedMemorySize, SMEM_REQ);

    const long long MM = 1024LL * 1024;

    // 1) inputs and weights -> f16
    {
        ConvArgs in;
        in.x[0] = query; in.h[0] = xqh;
        in.x[1] = key;   in.h[1] = xkh;
        in.x[2] = value; in.h[2] = xvh;
        convert3_kernel<<<dim3(16384, 3), 256>>>(in);
        ConvArgs w;
        w.x[0] = wq; w.h[0] = wqh;
        w.x[1] = wk; w.h[1] = wkh;
        w.x[2] = wv; w.h[2] = wvh;
        convert3_kernel<<<dim3(1024, 3), 256>>>(w);
    }

    // 2) merged projections: f = acc + bias
    //    q, k -> f16 batch-major (mode 5); v -> fp32 row-major (mode 0).
    {
        GArgs a = {};
        a.Ah[0] = xqh; a.Bh[0] = wqh;
        a.Ah[1] = xkh; a.Bh[1] = wkh;
        a.Ah[2] = xvh; a.Bh[2] = wvh;
        a.Ch[0] = qh;
        a.Ch[1] = kh;
        a.Cf[2] = vf;
        a.bias[0] = bias; a.bias[1] = bias + 1024; a.bias[2] = bias + 2048;
        a.mode[0] = 5; a.mode[1] = 5; a.mode[2] = 0;
        a.lda = 1024; a.ldb = 1024; a.ldc = 1024;
        a.sA = 0; a.sB = 0; a.sC = 0;
        a.K = 1024; a.batched = 0; a.ascale = 1.0f;
        gemm_f16<<<dim3(8, 128, 3), 256, SMEM_REQ>>>(a);
    }

    // 3) V transpose + convert
    transpose_conv_kernel<<<dim3(16, 16, 16), 256>>>(vf, vth);

    // 4) scores (fp16) + fused exp/partial-rowsum
    {
        GArgs a = {};
        a.Ah[0] = qh; a.Bh[0] = kh;
        a.Ch[0] = ath;
        a.mode[0] = 2;
        a.lda = 1024; a.ldb = 1024; a.ldc = 1024;
        a.sA = 1LL << 20; a.sB = 1LL << 20; a.sC = MM;
        a.K = 1024; a.batched = 1; a.ascale = 1.0f / 32.0f;
        a.part = part;
        gemm_f16<<<dim3(8, 8, 16), 256, SMEM_REQ>>>(a);
    }

    // 5) row-sum reciprocal
    rowsum_kernel<<<64, 256>>>(part, rsum);

    // 6) out = (e @ vt^T) * rsum[row]
    {
        GArgs a = {};
        a.Ah[0] = ath; a.Bh[0] = vth;
        a.Cf[0] = out;
        a.mode[0] = 3;
        a.lda = 1024; a.ldb = 1024; a.ldc = 16384;
        a.sA = MM; a.sB = MM; a.sC = 1024;
        a.K = 1024; a.batched = 1; a.ascale = 1.0f;
        a.rsum = rsum;
        gemm_f16<<<dim3(8, 8, 16), 256, SMEM_REQ>>>(a);
    }
}

// round 14
// speedup vs baseline: 2.9290x; 1.0695x over previous
#include <cuda_runtime.h>
#include <cuda_fp16.h>
#include <cstdint>

// ---------------------------------------------------------------------------
// CLIPDecoder_83786222011049 — single-head MHA forward.
// Round 14: pure-fp16 GEMMs (5 units); V projected directly to f16 (no fp32
// round-trip); ×4-unrolled converts (MLP); 4-stage cp.async pipeline.
// q/k batch-major; SW64 swizzle; ldmatrix; fused exp/rowsum softmax.
// ---------------------------------------------------------------------------

static constexpr int BM = 128, BN = 128, BK = 32;
static constexpr int TILE_B = 128 * 64;             // 8192 B per tile
static constexpr int STAGE_B = 2 * TILE_B;          // Ah, Bh = 16384
static constexpr int NSTAGE = 4;
static constexpr int SMEM_REQ = NSTAGE * STAGE_B;   // 65536 -> 2 CTAs/SM

// ---------------------------------------------------------------------------
// Scratch (device globals).
// ---------------------------------------------------------------------------
#define BIGH (size_t)(16384) * 1024
#define BATH (size_t)(16) * 1024 * 1024
__device__ __align__(256) __half g_xq_h[BIGH];
__device__ __align__(256) __half g_xk_h[BIGH];
__device__ __align__(256) __half g_xv_h[BIGH];
__device__ __align__(256) __half g_wq_h[1024*1024];
__device__ __align__(256) __half g_wk_h[1024*1024];
__device__ __align__(256) __half g_wv_h[1024*1024];
__device__ __align__(256) __half g_q_h[BIGH];                     // [nb][l][e]
__device__ __align__(256) __half g_k_h[BIGH];                     // [nb][l][e]
__device__ __align__(256) __half g_v_h[BIGH];                     // [(l*16+nb)][f]
__device__ __align__(256) __half g_vt_h[BATH];                    // [nb][f][s]
__device__ __align__(256) __half g_a_h[BATH];                     // [nb][l][s]
__device__ __align__(256) float  g_part[(size_t)16 * 1024 * 8];
__device__ __align__(256) float  g_rsum[(size_t)16 * 1024];

// ---------------------------------------------------------------------------
// PTX helpers
// ---------------------------------------------------------------------------
__device__ __forceinline__ void cp16(uint32_t sdst, const void* gsrc) {
    asm volatile("cp.async.cg.shared.global [%0], [%1], 16;\n"
                 :: "r"(sdst), "l"(gsrc));
}
__device__ __forceinline__ void cp_commit() {
    asm volatile("cp.async.commit_group;\n" ::: "memory");
}
template <int N> __device__ __forceinline__ void cp_wait() {
    asm volatile("cp.async.wait_group %0;\n" :: "n"(N) : "memory");
}
__device__ __forceinline__ void ldsm4(uint32_t* r, uint32_t addr) {
    asm volatile("ldmatrix.sync.aligned.m8n8.x4.shared.b16 {%0,%1,%2,%3}, [%4];"
                 : "=r"(r[0]), "=r"(r[1]), "=r"(r[2]), "=r"(r[3]) : "r"(addr));
}
__device__ __forceinline__ void mma16(float* d, const uint32_t* a, const uint32_t* b) {
    asm volatile(
        "mma.sync.aligned.m16n8k16.row.col.f32.f16.f16.f32 "
        "{%0,%1,%2,%3},{%4,%5,%6,%7},{%8,%9},{%0,%1,%2,%3};\n"
        : "+f"(d[0]), "+f"(d[1]), "+f"(d[2]), "+f"(d[3])
        : "r"(a[0]), "r"(a[1]), "r"(a[2]), "r"(a[3]), "r"(b[0]), "r"(b[1]));
}
__device__ __forceinline__ uint32_t pk2h(float a, float b) {
    __half2 t = __floats2half2_rn(a, b);
    return *reinterpret_cast<uint32_t*>(&t);
}

extern __shared__ char dynsm[];

// ---------------------------------------------------------------------------
// GEMM (NT), fp16: D = Ah*Bh.
// batched==0: blockIdx.z selects operand set. batched==1: z = batch index.
// mode: 2 exp epilogue: f16 out + row-sum partials
//       3 fp32 out * rsum[row]
//       5 f16 out, batch-transposed [nb][l][e] (+bias)
//       6 f16 out, row-major (+bias)
// SMEM: 64B rows, SW64 swizzle (byte16-col ^ ((row&6)<<3)).
// ---------------------------------------------------------------------------
struct GArgs {
    const __half* Ah[3];
    const __half* Bh[3];
    float* Cf[3]; __half* Ch[3];
    const float* bias[3];
    int mode[3];
    long long lda, ldb, ldc;
    long long sA, sB, sC;
    int K, batched;
    float ascale;
    float* part;
    const float* rsum;
};

__global__ __launch_bounds__(256, 2) void gemm_f16(GArgs p)
{
    constexpr int AH_O = 0, BH_O = TILE_B;

    const uint32_t sbase = (uint32_t)__cvta_generic_to_shared(dynsm);
    const int tid = threadIdx.x, lane = tid & 31, warp = tid >> 5;
    const int wm = warp & 1, wn = warp >> 1;      // 2(m) x 4(n) warps
    const int q = lane & 3, g = lane >> 2;

    const int zi = p.batched ? 0 : (int)blockIdx.z;
    const long long bz = p.batched ? (long long)blockIdx.z : 0;
    const int mode = p.mode[zi];

    const long long m0 = (long long)blockIdx.y * BM;
    const long long n0 = (long long)blockIdx.x * BN;

    const char* Ahb = (const char*)(p.Ah[zi] + bz * p.sA + m0 * p.lda);
    const char* Bhb = (const char*)(p.Bh[zi] + bz * p.sB + n0 * p.ldb);

    // ldmatrix lane addressing (SW64)
    const int a_row = wm * 64 + (lane & 15);
    const uint32_t a_base = (uint32_t)(a_row * 64);
    const uint32_t a_cs = (uint32_t)(((lane >> 4) << 4) ^ ((a_row & 6) << 3));
    const int b_row = wn * 32 + ((lane >> 4) & 1) * 8 + (lane & 7);
    const uint32_t b_base = (uint32_t)(b_row * 64);
    const uint32_t b_cs = (uint32_t)((((lane >> 3) & 1) << 4) ^ ((b_row & 6) << 3));

    float acc[4][4][4];
    #pragma unroll
    for (int i = 0; i < 4; ++i)
        #pragma unroll
        for (int j = 0; j < 4; ++j)
            #pragma unroll
            for (int r = 0; r < 4; ++r) acc[i][j][r] = 0.0f;

    const int KT = p.K / BK;
    const long long lda2 = p.lda * 2, ldb2 = p.ldb * 2;

    const int srow = tid >> 2;
    const uint32_t sc16 = (uint32_t)(((tid & 3) << 4) ^ ((srow & 6) << 3));

    auto load_tile = [&](int kt) {
        const uint32_t sb = sbase + (kt % NSTAGE) * STAGE_B;
        const long long kb = (long long)kt * (BK * 2);
        #pragma unroll
        for (int pp = 0; pp < 2; ++pp) {
            const int r = srow + pp * 64;
            const uint32_t d = (uint32_t)(r * 64) + sc16;
            const long long ga = (long long)r * lda2 + kb + ((tid & 3) << 4);
            const long long gb = (long long)r * ldb2 + kb + ((tid & 3) << 4);
            cp16(sb + AH_O + d, Ahb + ga);
            cp16(sb + BH_O + d, Bhb + gb);
        }
        cp_commit();
    };

    auto compute = [&](int kt) {
        const uint32_t sb = sbase + (kt % NSTAGE) * STAGE_B;
        #pragma unroll
        for (int kk = 0; kk < 2; ++kk) {
            const uint32_t ka = kk * 32;
            const uint32_t aoff = a_base + (ka ^ a_cs);
            const uint32_t boff = b_base + (ka ^ b_cs);
            uint32_t ah[4][4];
            #pragma unroll
            for (int i = 0; i < 4; ++i)
                ldsm4(ah[i], sb + AH_O + aoff + i * 1024);
            uint32_t bh[4][2];
            #pragma unroll
            for (int jp = 0; jp < 2; ++jp) {
                uint32_t rb[4];
                ldsm4(rb, sb + BH_O + boff + jp * 1024);
                bh[2*jp][0] = rb[0]; bh[2*jp][1] = rb[1];
                bh[2*jp+1][0] = rb[2]; bh[2*jp+1][1] = rb[3];
            }
            #pragma unroll
            for (int i = 0; i < 4; ++i)
                #pragma unroll
                for (int j = 0; j < 4; ++j)
                    mma16(acc[i][j], ah[i], bh[j]);
        }
    };

    // 4-stage pipeline, prefetch distance 3.
    load_tile(0);
    load_tile(1);
    load_tile(2);
    for (int kt = 0; kt < KT; ++kt) {
        cp_wait<2>();
        __syncthreads();
        if (kt + 3 < KT) load_tile(kt + 3);
        else             cp_commit();
        compute(kt);
    }

    // ---------------- epilogues ----------------
    if (mode == 2) {
        __syncthreads();
        float (*srows)[4] = reinterpret_cast<float(*)[4]>(dynsm);
        __half* Ch = p.Ch[zi];
        #pragma unroll
        for (int i = 0; i < 4; ++i) {
            float p0 = 0.0f, p1 = 0.0f;
            const long long r0 = m0 + wm * 64 + i * 16 + g;
            #pragma unroll
            for (int j = 0; j < 4; ++j) {
                float e0 = __expf(acc[i][j][0] * p.ascale);
                float e1 = __expf(acc[i][j][1] * p.ascale);
                float e2 = __expf(acc[i][j][2] * p.ascale);
                float e3 = __expf(acc[i][j][3] * p.ascale);
                p0 += e0 + e1;  p1 += e2 + e3;
                const long long c0 = n0 + wn * 32 + j * 8 + 2 * q;
                *(uint32_t*)(Ch + bz * p.sC + r0 * p.ldc + c0)       = pk2h(e0, e1);
                *(uint32_t*)(Ch + bz * p.sC + (r0 + 8) * p.ldc + c0) = pk2h(e2, e3);
            }
            p0 += __shfl_xor_sync(0xFFFFFFFFu, p0, 1);
            p0 += __shfl_xor_sync(0xFFFFFFFFu, p0, 2);
            p1 += __shfl_xor_sync(0xFFFFFFFFu, p1, 1);
            p1 += __shfl_xor_sync(0xFFFFFFFFu, p1, 2);
            if (q == 0) {
                srows[wm * 64 + i * 16 + g][wn]     = p0;
                srows[wm * 64 + i * 16 + g + 8][wn] = p1;
            }
        }
        __syncthreads();
        if (tid < 128) {
            float s = srows[tid][0] + srows[tid][1] + srows[tid][2] + srows[tid][3];
            p.part[((bz << 10) + m0 + tid) * 8 + blockIdx.x] = s;
        }
        return;
    }

    if (mode == 3) {
        float* Cf = p.Cf[zi];
        #pragma unroll
        for (int i = 0; i < 4; ++i) {
            const long long r0 = m0 + wm * 64 + i * 16 + g;
            const float rs0 = p.rsum[(bz << 10) + r0];
            const float rs1 = p.rsum[(bz << 10) + r0 + 8];
            #pragma unroll
            for (int j = 0; j < 4; ++j) {
                const long long c0 = n0 + wn * 32 + j * 8 + 2 * q;
                *(float2*)(Cf + bz * p.sC + r0 * p.ldc + c0) =
                    make_float2(acc[i][j][0] * rs0, acc[i][j][1] * rs0);
                *(float2*)(Cf + bz * p.sC + (r0 + 8) * p.ldc + c0) =
                    make_float2(acc[i][j][2] * rs1, acc[i][j][3] * rs1);
            }
        }
        return;
    }

    // modes 5 / 6: f16 out, f = acc + bias
    const float* bias = p.bias[zi];
    __half* Ch = p.Ch[zi];
    #pragma unroll
    for (int i = 0; i < 4; ++i) {
        const long long r0 = m0 + wm * 64 + i * 16 + g;
        const long long r1 = r0 + 8;
        long long t0, t1;
        if (mode == 5) {    // batch-transposed [nb][l][e]
            t0 = ((r0 & 15) << 20) + ((r0 >> 4) << 10);
            t1 = ((r1 & 15) << 20) + ((r1 >> 4) << 10);
        } else {            // row-major
            t0 = r0 * p.ldc;
            t1 = r1 * p.ldc;
        }
        #pragma unroll
        for (int j = 0; j < 4; ++j) {
            const long long c0 = n0 + wn * 32 + j * 8 + 2 * q;
            const float b0 = bias[c0];
            const float b1 = bias[c0 + 1];
            *(uint32_t*)(Ch + t0 + c0) = pk2h(acc[i][j][0] + b0, acc[i][j][1] + b1);
            *(uint32_t*)(Ch + t1 + c0) = pk2h(acc[i][j][2] + b0, acc[i][j][3] + b1);
        }
    }
}

// ---------------------------------------------------------------------------
// fp32 -> f16, 3 arrays fused via blockIdx.y; 4 float4 per thread (MLP=4).
// n per array must be a multiple of 4096.
// ---------------------------------------------------------------------------
struct ConvArgs {
    const float* x[3];
    __half* h[3];
};

__global__ __launch_bounds__(256) void convert3_kernel(ConvArgs args)
{
    const int a = blockIdx.y;
    const float4* src = (const float4*)args.x[a];
    uint2* dst = (uint2*)args.h[a];
    const long long i0 = (long long)blockIdx.x * 1024 + threadIdx.x;
    float4 v0 = src[i0];
    float4 v1 = src[i0 + 256];
    float4 v2 = src[i0 + 512];
    float4 v3 = src[i0 + 768];
    dst[i0]       = make_uint2(pk2h(v0.x, v0.y), pk2h(v0.z, v0.w));
    dst[i0 + 256] = make_uint2(pk2h(v1.x, v1.y), pk2h(v1.z, v1.w));
    dst[i0 + 512] = make_uint2(pk2h(v2.x, v2.y), pk2h(v2.z, v2.w));
    dst[i0 + 768] = make_uint2(pk2h(v3.x, v3.y), pk2h(v3.z, v3.w));
}

// ---------------------------------------------------------------------------
// Transpose V (f16 -> f16):  v[(s*16+nb)*1024 + f] -> vt[nb][f][s]
// ---------------------------------------------------------------------------
__global__ __launch_bounds__(256) void transpose_kernel(
    const __half* __restrict__ v, __half* __restrict__ vt)
{
    __shared__ __half t[64][72];
    const int nb = blockIdx.z;
    const int s0 = blockIdx.x * 64, f0 = blockIdx.y * 64;
    const int c = threadIdx.x & 63, r0 = threadIdx.x >> 6;

    #pragma unroll
    for (int rr = r0; rr < 64; rr += 4)
        t[rr][c] = v[(long long)((s0 + rr) * 16 + nb) * 1024 + f0 + c];
    __syncthreads();

    __half* o = vt + (size_t)nb * 1024 * 1024;
    #pragma unroll
    for (int rr = r0; rr < 64; rr += 4)
        o[(size_t)(f0 + rr) * 1024 + s0 + c] = t[c][rr];
}

// ---------------------------------------------------------------------------
// rsum[row] = 1 / sum_{cb<8} part[row*8+cb]
// ---------------------------------------------------------------------------
__global__ __launch_bounds__(256) void rowsum_kernel(
    const float* __restrict__ part, float* __restrict__ rsum)
{
    const int row = blockIdx.x * 256 + threadIdx.x;
    const float4 a = ((const float4*)part)[row * 2];
    const float4 b = ((const float4*)part)[row * 2 + 1];
    rsum[row] = 1.0f / (((a.x + a.y) + (a.z + a.w)) + ((b.x + b.y) + (b.z + b.w)));
}

// ---------------------------------------------------------------------------
// Launch
// ---------------------------------------------------------------------------
extern "C" void kernel_launch(void* const* d_in, const int* in_sizes, int n_in,
                              void* d_out, int out_size)
{
    const float* query = (const float*)d_in[0];
    const float* key   = (const float*)d_in[1];
    const float* value = (const float*)d_in[2];
    const float* wq    = (const float*)d_in[3];
    const float* wk    = (const float*)d_in[4];
    const float* wv    = (const float*)d_in[5];
    const float* bias  = (const float*)d_in[6];
    float* out = (float*)d_out;

    __half *xqh,*xkh,*xvh, *wqh,*wkh,*wvh;
    __half *qh,*kh,*vh,*vth,*ath;
    float *part, *rsum;
    cudaGetSymbolAddress((void**)&xqh, g_xq_h);
    cudaGetSymbolAddress((void**)&xkh, g_xk_h);
    cudaGetSymbolAddress((void**)&xvh, g_xv_h);
    cudaGetSymbolAddress((void**)&wqh, g_wq_h);
    cudaGetSymbolAddress((void**)&wkh, g_wk_h);
    cudaGetSymbolAddress((void**)&wvh, g_wv_h);
    cudaGetSymbolAddress((void**)&qh,  g_q_h);
    cudaGetSymbolAddress((void**)&kh,  g_k_h);
    cudaGetSymbolAddress((void**)&vh,  g_v_h);
    cudaGetSymbolAddress((void**)&vth, g_vt_h);
    cudaGetSymbolAddress((void**)&ath, g_a_h);
    cudaGetSymbolAddress((void**)&part, g_part);
    cudaGetSymbolAddress((void**)&rsum, g_rsum);

    cudaFuncSetAttribute(gemm_f16, cudaFuncAttributeMaxDynamicSharedMemorySize, SMEM_REQ);

    const long long MM = 1024LL * 1024;

    // 1) inputs and weights -> f16
    {
        ConvArgs in;
        in.x[0] = query; in.h[0] = xqh;
        in.x[1] = key;   in.h[1] = xkh;
        in.x[2] = value; in.h[2] = xvh;
        convert3_kernel<<<dim3(4096, 3), 256>>>(in);
        ConvArgs w;
        w.x[0] = wq; w.h[0] = wqh;
        w.x[1] = wk; w.h[1] = wkh;
        w.x[2] = wv; w.h[2] = wvh;
        convert3_kernel<<<dim3(256, 3), 256>>>(w);
    }

    // 2) merged projections: f = acc + bias
    //    q, k -> f16 batch-major (mode 5); v -> f16 row-major (mode 6).
    {
        GArgs a = {};
        a.Ah[0] = xqh; a.Bh[0] = wqh;
        a.Ah[1] = xkh; a.Bh[1] = wkh;
        a.Ah[2] = xvh; a.Bh[2] = wvh;
        a.Ch[0] = qh;
        a.Ch[1] = kh;
        a.Ch[2] = vh;
        a.bias[0] = bias; a.bias[1] = bias + 1024; a.bias[2] = bias + 2048;
        a.mode[0] = 5; a.mode[1] = 5; a.mode[2] = 6;
        a.lda = 1024; a.ldb = 1024; a.ldc = 1024;
        a.sA = 0; a.sB = 0; a.sC = 0;
        a.K = 1024; a.batched = 0; a.ascale = 1.0f;
        gemm_f16<<<dim3(8, 128, 3), 256, SMEM_REQ>>>(a);
    }

    // 3) V transpose (f16 -> f16)
    transpose_kernel<<<dim3(16, 16, 16), 256>>>(vh, vth);

    // 4) scores (fp16) + fused exp/partial-rowsum
    {
        GArgs a = {};
        a.Ah[0] = qh; a.Bh[0] = kh;
        a.Ch[0] = ath;
        a.mode[0] = 2;
        a.lda = 1024; a.ldb = 1024; a.ldc = 1024;
        a.sA = 1LL << 20; a.sB = 1LL << 20; a.sC = MM;
        a.K = 1024; a.batched = 1; a.ascale = 1.0f / 32.0f;
        a.part = part;
        gemm_f16<<<dim3(8, 8, 16), 256, SMEM_REQ>>>(a);
    }

    // 5) row-sum reciprocal
    rowsum_kernel<<<64, 256>>>(part, rsum);

    // 6) out = (e @ vt^T) * rsum[row]
    {
        GArgs a = {};
        a.Ah[0] = ath; a.Bh[0] = vth;
        a.Cf[0] = out;
        a.mode[0] = 3;
        a.lda = 1024; a.ldb = 1024; a.ldc = 16384;
        a.sA = MM; a.sB = MM; a.sC = 1024;
        a.K = 1024; a.batched = 1; a.ascale = 1.0f;
        a.rsum = rsum;
        gemm_f16<<<dim3(8, 8, 16), 256, SMEM_REQ>>>(a);
    }
}

// round 15
// speedup vs baseline: 3.0335x; 1.0357x over previous
#include <cuda_runtime.h>
#include <cuda_fp16.h>
#include <cstdint>

// ---------------------------------------------------------------------------
// CLIPDecoder_83786222011049 — single-head MHA forward.
// Round 15: pure-fp16 GEMMs (5 units). AV GEMM reads V directly (NN path,
// ldmatrix.trans) -> V-transpose kernel eliminated; rowsum fused into the
// AV epilogue. q/k batch-major; SW64 swizzle; 4-stage cp.async; fused
// exp/rowsum-partial softmax.
// ---------------------------------------------------------------------------

static constexpr int BM = 128, BN = 128, BK = 32;
static constexpr int TILE_B = 8192;                 // per tile (A or B)
static constexpr int STAGE_B = 2 * TILE_B;          // 16384
static constexpr int NSTAGE = 4;
static constexpr int SMEM_REQ = NSTAGE * STAGE_B;   // 65536 -> 2 CTAs/SM

// ---------------------------------------------------------------------------
// Scratch (device globals).
// ---------------------------------------------------------------------------
#define BIGH (size_t)(16384) * 1024
#define BATH (size_t)(16) * 1024 * 1024
__device__ __align__(256) __half g_xq_h[BIGH];
__device__ __align__(256) __half g_xk_h[BIGH];
__device__ __align__(256) __half g_xv_h[BIGH];
__device__ __align__(256) __half g_wq_h[1024*1024];
__device__ __align__(256) __half g_wk_h[1024*1024];
__device__ __align__(256) __half g_wv_h[1024*1024];
__device__ __align__(256) __half g_q_h[BIGH];                     // [nb][l][e]
__device__ __align__(256) __half g_k_h[BIGH];                     // [nb][l][e]
__device__ __align__(256) __half g_v_h[BIGH];                     // [(s*16+nb)][f]
__device__ __align__(256) __half g_a_h[BATH];                     // [nb][l][s]
__device__ __align__(256) float  g_part[(size_t)16 * 1024 * 8];

// ---------------------------------------------------------------------------
// PTX helpers
// ---------------------------------------------------------------------------
__device__ __forceinline__ void cp16(uint32_t sdst, const void* gsrc) {
    asm volatile("cp.async.cg.shared.global [%0], [%1], 16;\n"
                 :: "r"(sdst), "l"(gsrc));
}
__device__ __forceinline__ void cp_commit() {
    asm volatile("cp.async.commit_group;\n" ::: "memory");
}
template <int N> __device__ __forceinline__ void cp_wait() {
    asm volatile("cp.async.wait_group %0;\n" :: "n"(N) : "memory");
}
__device__ __forceinline__ void ldsm4(uint32_t* r, uint32_t addr) {
    asm volatile("ldmatrix.sync.aligned.m8n8.x4.shared.b16 {%0,%1,%2,%3}, [%4];"
                 : "=r"(r[0]), "=r"(r[1]), "=r"(r[2]), "=r"(r[3]) : "r"(addr));
}
__device__ __forceinline__ void ldsm4t(uint32_t* r, uint32_t addr) {
    asm volatile("ldmatrix.sync.aligned.m8n8.x4.trans.shared.b16 {%0,%1,%2,%3}, [%4];"
                 : "=r"(r[0]), "=r"(r[1]), "=r"(r[2]), "=r"(r[3]) : "r"(addr));
}
__device__ __forceinline__ void mma16(float* d, const uint32_t* a, const uint32_t* b) {
    asm volatile(
        "mma.sync.aligned.m16n8k16.row.col.f32.f16.f16.f32 "
        "{%0,%1,%2,%3},{%4,%5,%6,%7},{%8,%9},{%0,%1,%2,%3};\n"
        : "+f"(d[0]), "+f"(d[1]), "+f"(d[2]), "+f"(d[3])
        : "r"(a[0]), "r"(a[1]), "r"(a[2]), "r"(a[3]), "r"(b[0]), "r"(b[1]));
}
__device__ __forceinline__ uint32_t pk2h(float a, float b) {
    __half2 t = __floats2half2_rn(a, b);
    return *reinterpret_cast<uint32_t*>(&t);
}

extern __shared__ char dynsm[];

// ---------------------------------------------------------------------------
// GEMM, fp16, D = A*B'.
//  BTRANS=0 (NT): B is NxK k-contiguous (rows n, 64B, SW64 swizzle).
//  BTRANS=1 (NN): B is KxN n-contiguous (rows k, 256B, chunk^k swizzle),
//                 loaded with ldmatrix.trans.
// batched==0: blockIdx.z selects operand set. batched==1: z = batch index.
// mode: 2 exp epilogue: f16 out + row-sum partials
//       3 fp32 out * (1/rowsum) with rowsum summed from partials in-epilogue
//       5 f16 out, batch-transposed [nb][l][e] (+bias)
//       6 f16 out, row-major (+bias)
// ---------------------------------------------------------------------------
struct GArgs {
    const __half* Ah[3];
    const __half* Bh[3];
    float* Cf[3]; __half* Ch[3];
    const float* bias[3];
    int mode[3];
    long long lda, ldb, ldc;
    long long sA, sB, sC;
    int K, batched;
    float ascale;
    float* part;
};

template <int BTRANS>
__global__ __launch_bounds__(256, 2) void gemm_f16(GArgs p)
{
    constexpr int AH_O = 0, BH_O = TILE_B;

    const uint32_t sbase = (uint32_t)__cvta_generic_to_shared(dynsm);
    const int tid = threadIdx.x, lane = tid & 31, warp = tid >> 5;
    const int wm = warp & 1, wn = warp >> 1;      // 2(m) x 4(n) warps
    const int q = lane & 3, g = lane >> 2;

    const int zi = p.batched ? 0 : (int)blockIdx.z;
    const long long bz = p.batched ? (long long)blockIdx.z : 0;
    const int mode = p.mode[zi];

    const long long m0 = (long long)blockIdx.y * BM;
    const long long n0 = (long long)blockIdx.x * BN;

    const char* Ahb = (const char*)(p.Ah[zi] + bz * p.sA + m0 * p.lda);
    // NT: row n base; NN: element base (batch + n offset), rows advance by ldb.
    const char* Bhb = BTRANS
        ? (const char*)(p.Bh[zi] + bz * p.sB + n0)
        : (const char*)(p.Bh[zi] + bz * p.sB + n0 * p.ldb);

    // A ldmatrix lane addressing (SW64)
    const int a_row = wm * 64 + (lane & 15);
    const uint32_t a_base = (uint32_t)(a_row * 64);
    const uint32_t a_cs = (uint32_t)(((lane >> 4) << 4) ^ ((a_row & 6) << 3));
    // B NT lane addressing (SW64)
    const int b_row = wn * 32 + ((lane >> 4) & 1) * 8 + (lane & 7);
    const uint32_t b_base = (uint32_t)(b_row * 64);
    const uint32_t b_cs = (uint32_t)((((lane >> 3) & 1) << 4) ^ ((b_row & 6) << 3));
    // B NN (trans) lane addressing: rows k (256B), chunk ^= (k&7)
    const int bt_krow = lane & 15;                 // + kk*16
    const uint32_t bt_kx = (uint32_t)(lane & 7);   // k&7 (kk*16 ≡ 0 mod 8)

    float acc[4][4][4];
    #pragma unroll
    for (int i = 0; i < 4; ++i)
        #pragma unroll
        for (int j = 0; j < 4; ++j)
            #pragma unroll
            for (int r = 0; r < 4; ++r) acc[i][j][r] = 0.0f;

    const int KT = p.K / BK;
    const long long lda2 = p.lda * 2, ldb2 = p.ldb * 2;

    const int srow = tid >> 2;
    const uint32_t sc16 = (uint32_t)(((tid & 3) << 4) ^ ((srow & 6) << 3));

    auto load_tile = [&](int kt) {
        const uint32_t sb = sbase + (kt % NSTAGE) * STAGE_B;
        const long long kb = (long long)kt * (BK * 2);
        // A tile: 128 rows x 64 B, SW64
        #pragma unroll
        for (int pp = 0; pp < 2; ++pp) {
            const int r = srow + pp * 64;
            const uint32_t d = (uint32_t)(r * 64) + sc16;
            cp16(sb + AH_O + d,
                 Ahb + (long long)r * lda2 + kb + ((tid & 3) << 4));
        }
        if (BTRANS == 0) {
            #pragma unroll
            for (int pp = 0; pp < 2; ++pp) {
                const int r = srow + pp * 64;
                const uint32_t d = (uint32_t)(r * 64) + sc16;
                cp16(sb + BH_O + d,
                     Bhb + (long long)r * ldb2 + kb + ((tid & 3) << 4));
            }
        } else {
            // B tile: 32 k-rows x 256 B, chunk ^= (k&7). 512 chunks.
            #pragma unroll
            for (int pp = 0; pp < 2; ++pp) {
                const int c = tid + pp * 256;
                const int k = c >> 4, c16 = c & 15;
                const uint32_t d = (uint32_t)(k * 256 + ((c16 ^ (k & 7)) << 4));
                cp16(sb + BH_O + d,
                     Bhb + (long long)(kt * BK + k) * ldb2 + ((long long)c16 << 4));
            }
        }
        cp_commit();
    };

    auto compute = [&](int kt) {
        const uint32_t sb = sbase + (kt % NSTAGE) * STAGE_B;
        #pragma unroll
        for (int kk = 0; kk < 2; ++kk) {
            const uint32_t ka = kk * 32;
            const uint32_t aoff = a_base + (ka ^ a_cs);
            uint32_t ah[4][4];
            #pragma unroll
            for (int i = 0; i < 4; ++i)
                ldsm4(ah[i], sb + AH_O + aoff + i * 1024);
            uint32_t bh[4][2];
            if (BTRANS == 0) {
                const uint32_t boff = b_base + (ka ^ b_cs);
                #pragma unroll
                for (int jp = 0; jp < 2; ++jp) {
                    uint32_t rb[4];
                    ldsm4(rb, sb + BH_O + boff + jp * 1024);
                    bh[2*jp][0] = rb[0]; bh[2*jp][1] = rb[1];
                    bh[2*jp+1][0] = rb[2]; bh[2*jp+1][1] = rb[3];
                }
            } else {
                const uint32_t krow = (uint32_t)(kk * 16 + bt_krow) * 256;
                #pragma unroll
                for (int jp = 0; jp < 2; ++jp) {
                    const uint32_t ch = (uint32_t)(wn * 4 + jp * 2 + (lane >> 4));
                    uint32_t rb[4];
                    ldsm4t(rb, sb + BH_O + krow + ((ch ^ bt_kx) << 4));
                    bh[2*jp][0] = rb[0]; bh[2*jp][1] = rb[1];
                    bh[2*jp+1][0] = rb[2]; bh[2*jp+1][1] = rb[3];
                }
            }
            #pragma unroll
            for (int i = 0; i < 4; ++i)
                #pragma unroll
                for (int j = 0; j < 4; ++j)
                    mma16(acc[i][j], ah[i], bh[j]);
        }
    };

    // 4-stage pipeline, prefetch distance 3.
    load_tile(0);
    load_tile(1);
    load_tile(2);
    for (int kt = 0; kt < KT; ++kt) {
        cp_wait<2>();
        __syncthreads();
        if (kt + 3 < KT) load_tile(kt + 3);
        else             cp_commit();
        compute(kt);
    }

    // ---------------- epilogues ----------------
    if (mode == 2) {
        __syncthreads();
        float (*srows)[4] = reinterpret_cast<float(*)[4]>(dynsm);
        __half* Ch = p.Ch[zi];
        #pragma unroll
        for (int i = 0; i < 4; ++i) {
            float p0 = 0.0f, p1 = 0.0f;
            const long long r0 = m0 + wm * 64 + i * 16 + g;
            #pragma unroll
            for (int j = 0; j < 4; ++j) {
                float e0 = __expf(acc[i][j][0] * p.ascale);
                float e1 = __expf(acc[i][j][1] * p.ascale);
                float e2 = __expf(acc[i][j][2] * p.ascale);
                float e3 = __expf(acc[i][j][3] * p.ascale);
                p0 += e0 + e1;  p1 += e2 + e3;
                const long long c0 = n0 + wn * 32 + j * 8 + 2 * q;
                *(uint32_t*)(Ch + bz * p.sC + r0 * p.ldc + c0)       = pk2h(e0, e1);
                *(uint32_t*)(Ch + bz * p.sC + (r0 + 8) * p.ldc + c0) = pk2h(e2, e3);
            }
            p0 += __shfl_xor_sync(0xFFFFFFFFu, p0, 1);
            p0 += __shfl_xor_sync(0xFFFFFFFFu, p0, 2);
            p1 += __shfl_xor_sync(0xFFFFFFFFu, p1, 1);
            p1 += __shfl_xor_sync(0xFFFFFFFFu, p1, 2);
            if (q == 0) {
                srows[wm * 64 + i * 16 + g][wn]     = p0;
                srows[wm * 64 + i * 16 + g + 8][wn] = p1;
            }
        }
        __syncthreads();
        if (tid < 128) {
            float s = srows[tid][0] + srows[tid][1] + srows[tid][2] + srows[tid][3];
            p.part[((bz << 10) + m0 + tid) * 8 + blockIdx.x] = s;
        }
        return;
    }

    if (mode == 3) {
        float* Cf = p.Cf[zi];
        #pragma unroll
        for (int i = 0; i < 4; ++i) {
            const long long r0 = m0 + wm * 64 + i * 16 + g;
            const float4 pa0 = ((const float4*)p.part)[((bz << 10) + r0) * 2];
            const float4 pb0 = ((const float4*)p.part)[((bz << 10) + r0) * 2 + 1];
            const float4 pa1 = ((const float4*)p.part)[((bz << 10) + r0 + 8) * 2];
            const float4 pb1 = ((const float4*)p.part)[((bz << 10) + r0 + 8) * 2 + 1];
            const float rs0 = 1.0f / (((pa0.x + pa0.y) + (pa0.z + pa0.w)) +
                                      ((pb0.x + pb0.y) + (pb0.z + pb0.w)));
            const float rs1 = 1.0f / (((pa1.x + pa1.y) + (pa1.z + pa1.w)) +
                                      ((pb1.x + pb1.y) + (pb1.z + pb1.w)));
            #pragma unroll
            for (int j = 0; j < 4; ++j) {
                const long long c0 = n0 + wn * 32 + j * 8 + 2 * q;
                *(float2*)(Cf + bz * p.sC + r0 * p.ldc + c0) =
                    make_float2(acc[i][j][0] * rs0, acc[i][j][1] * rs0);
                *(float2*)(Cf + bz * p.sC + (r0 + 8) * p.ldc + c0) =
                    make_float2(acc[i][j][2] * rs1, acc[i][j][3] * rs1);
            }
        }
        return;
    }

    // modes 5 / 6: f16 out, f = acc + bias
    const float* bias = p.bias[zi];
    __half* Ch = p.Ch[zi];
    #pragma unroll
    for (int i = 0; i < 4; ++i) {
        const long long r0 = m0 + wm * 64 + i * 16 + g;
        const long long r1 = r0 + 8;
        long long t0, t1;
        if (mode == 5) {    // batch-transposed [nb][l][e]
            t0 = ((r0 & 15) << 20) + ((r0 >> 4) << 10);
            t1 = ((r1 & 15) << 20) + ((r1 >> 4) << 10);
        } else {            // row-major
            t0 = r0 * p.ldc;
            t1 = r1 * p.ldc;
        }
        #pragma unroll
        for (int j = 0; j < 4; ++j) {
            const long long c0 = n0 + wn * 32 + j * 8 + 2 * q;
            const float b0 = bias[c0];
            const float b1 = bias[c0 + 1];
            *(uint32_t*)(Ch + t0 + c0) = pk2h(acc[i][j][0] + b0, acc[i][j][1] + b1);
            *(uint32_t*)(Ch + t1 + c0) = pk2h(acc[i][j][2] + b0, acc[i][j][3] + b1);
        }
    }
}

// ---------------------------------------------------------------------------
// fp32 -> f16, 3 arrays fused via blockIdx.y; 4 float4 per thread (MLP=4).
// n per array must be a multiple of 4096.
// ---------------------------------------------------------------------------
struct ConvArgs {
    const float* x[3];
    __half* h[3];
};

__global__ __launch_bounds__(256) void convert3_kernel(ConvArgs args)
{
    const int a = blockIdx.y;
    const float4* src = (const float4*)args.x[a];
    uint2* dst = (uint2*)args.h[a];
    const long long i0 = (long long)blockIdx.x * 1024 + threadIdx.x;
    float4 v0 = src[i0];
    float4 v1 = src[i0 + 256];
    float4 v2 = src[i0 + 512];
    float4 v3 = src[i0 + 768];
    dst[i0]       = make_uint2(pk2h(v0.x, v0.y), pk2h(v0.z, v0.w));
    dst[i0 + 256] = make_uint2(pk2h(v1.x, v1.y), pk2h(v1.z, v1.w));
    dst[i0 + 512] = make_uint2(pk2h(v2.x, v2.y), pk2h(v2.z, v2.w));
    dst[i0 + 768] = make_uint2(pk2h(v3.x, v3.y), pk2h(v3.z, v3.w));
}

// ---------------------------------------------------------------------------
// Launch
// ---------------------------------------------------------------------------
extern "C" void kernel_launch(void* const* d_in, const int* in_sizes, int n_in,
                              void* d_out, int out_size)
{
    const float* query = (const float*)d_in[0];
    const float* key   = (const float*)d_in[1];
    const float* value = (const float*)d_in[2];
    const float* wq    = (const float*)d_in[3];
    const float* wk    = (const float*)d_in[4];
    const float* wv    = (const float*)d_in[5];
    const float* bias  = (const float*)d_in[6];
    float* out = (float*)d_out;

    __half *xqh,*xkh,*xvh, *wqh,*wkh,*wvh;
    __half *qh,*kh,*vh,*ath;
    float *part;
    cudaGetSymbolAddress((void**)&xqh, g_xq_h);
    cudaGetSymbolAddress((void**)&xkh, g_xk_h);
    cudaGetSymbolAddress((void**)&xvh, g_xv_h);
    cudaGetSymbolAddress((void**)&wqh, g_wq_h);
    cudaGetSymbolAddress((void**)&wkh, g_wk_h);
    cudaGetSymbolAddress((void**)&wvh, g_wv_h);
    cudaGetSymbolAddress((void**)&qh,  g_q_h);
    cudaGetSymbolAddress((void**)&kh,  g_k_h);
    cudaGetSymbolAddress((void**)&vh,  g_v_h);
    cudaGetSymbolAddress((void**)&ath, g_a_h);
    cudaGetSymbolAddress((void**)&part, g_part);

    cudaFuncSetAttribute(gemm_f16<0>, cudaFuncAttributeMaxDynamicSharedMemorySize, SMEM_REQ);
    cudaFuncSetAttribute(gemm_f16<1>, cudaFuncAttributeMaxDynamicSharedMemorySize, SMEM_REQ);

    const long long MM = 1024LL * 1024;

    // 1) inputs and weights -> f16
    {
        ConvArgs in;
        in.x[0] = query; in.h[0] = xqh;
        in.x[1] = key;   in.h[1] = xkh;
        in.x[2] = value; in.h[2] = xvh;
        convert3_kernel<<<dim3(4096, 3), 256>>>(in);
        ConvArgs w;
        w.x[0] = wq; w.h[0] = wqh;
        w.x[1] = wk; w.h[1] = wkh;
        w.x[2] = wv; w.h[2] = wvh;
        convert3_kernel<<<dim3(256, 3), 256>>>(w);
    }

    // 2) merged projections: f = acc + bias
    //    q, k -> f16 batch-major (mode 5); v -> f16 row-major (mode 6).
    {
        GArgs a = {};
        a.Ah[0] = xqh; a.Bh[0] = wqh;
        a.Ah[1] = xkh; a.Bh[1] = wkh;
        a.Ah[2] = xvh; a.Bh[2] = wvh;
        a.Ch[0] = qh;
        a.Ch[1] = kh;
        a.Ch[2] = vh;
        a.bias[0] = bias; a.bias[1] = bias + 1024; a.bias[2] = bias + 2048;
        a.mode[0] = 5; a.mode[1] = 5; a.mode[2] = 6;
        a.lda = 1024; a.ldb = 1024; a.ldc = 1024;
        a.sA = 0; a.sB = 0; a.sC = 0;
        a.K = 1024; a.batched = 0; a.ascale = 1.0f;
        gemm_f16<0><<<dim3(8, 128, 3), 256, SMEM_REQ>>>(a);
    }

    // 3) scores (fp16) + fused exp/partial-rowsum
    {
        GArgs a = {};
        a.Ah[0] = qh; a.Bh[0] = kh;
        a.Ch[0] = ath;
        a.mode[0] = 2;
        a.lda = 1024; a.ldb = 1024; a.ldc = 1024;
        a.sA = 1LL << 20; a.sB = 1LL << 20; a.sC = MM;
        a.K = 1024; a.batched = 1; a.ascale = 1.0f / 32.0f;
        a.part = part;
        gemm_f16<0><<<dim3(8, 8, 16), 256, SMEM_REQ>>>(a);
    }

    // 4) out = (e @ V) * (1/rowsum)  — NN path reads V directly, rowsum fused
    {
        GArgs a = {};
        a.Ah[0] = ath; a.Bh[0] = vh;
        a.Cf[0] = out;
        a.mode[0] = 3;
        a.lda = 1024; a.ldb = 16384; a.ldc = 16384;
        a.sA = MM; a.sB = 1024; a.sC = 1024;
        a.K = 1024; a.batched = 1; a.ascale = 1.0f;
        a.part = part;
        gemm_f16<1><<<dim3(8, 8, 16), 256, SMEM_REQ>>>(a);
    }
}

// round 16
// speedup vs baseline: 3.2343x; 1.0662x over previous
#include <cuda_runtime.h>
#include <cuda_fp16.h>
#include <cstdint>

// ---------------------------------------------------------------------------
// CLIPDecoder_83786222011049 — single-head MHA forward.
// Round 16: BK=64 (half the barriers: 16 K-iterations), 128B SMEM rows with
// chunk^row swizzle; 3-stage cp.async. Pure-fp16 GEMMs (5 units); AV reads
// V directly (NN/trans); rowsum fused into AV epilogue; fused exp softmax.
// ---------------------------------------------------------------------------

static constexpr int BM = 128, BN = 128, BK = 64;
static constexpr int TILE_B = 128 * 128;            // 16384 B per tile
static constexpr int STAGE_B = 2 * TILE_B;          // 32768
static constexpr int NSTAGE = 3;
static constexpr int SMEM_REQ = NSTAGE * STAGE_B;   // 98304 -> 2 CTAs/SM

// ---------------------------------------------------------------------------
// Scratch (device globals).
// ---------------------------------------------------------------------------
#define BIGH (size_t)(16384) * 1024
#define BATH (size_t)(16) * 1024 * 1024
__device__ __align__(256) __half g_xq_h[BIGH];
__device__ __align__(256) __half g_xk_h[BIGH];
__device__ __align__(256) __half g_xv_h[BIGH];
__device__ __align__(256) __half g_wq_h[1024*1024];
__device__ __align__(256) __half g_wk_h[1024*1024];
__device__ __align__(256) __half g_wv_h[1024*1024];
__device__ __align__(256) __half g_q_h[BIGH];                     // [nb][l][e]
__device__ __align__(256) __half g_k_h[BIGH];                     // [nb][l][e]
__device__ __align__(256) __half g_v_h[BIGH];                     // [(s*16+nb)][f]
__device__ __align__(256) __half g_a_h[BATH];                     // [nb][l][s]
__device__ __align__(256) float  g_part[(size_t)16 * 1024 * 8];

// ---------------------------------------------------------------------------
// PTX helpers
// ---------------------------------------------------------------------------
__device__ __forceinline__ void cp16(uint32_t sdst, const void* gsrc) {
    asm volatile("cp.async.cg.shared.global [%0], [%1], 16;\n"
                 :: "r"(sdst), "l"(gsrc));
}
__device__ __forceinline__ void cp_commit() {
    asm volatile("cp.async.commit_group;\n" ::: "memory");
}
template <int N> __device__ __forceinline__ void cp_wait() {
    asm volatile("cp.async.wait_group %0;\n" :: "n"(N) : "memory");
}
__device__ __forceinline__ void ldsm4(uint32_t* r, uint32_t addr) {
    asm volatile("ldmatrix.sync.aligned.m8n8.x4.shared.b16 {%0,%1,%2,%3}, [%4];"
                 : "=r"(r[0]), "=r"(r[1]), "=r"(r[2]), "=r"(r[3]) : "r"(addr));
}
__device__ __forceinline__ void ldsm4t(uint32_t* r, uint32_t addr) {
    asm volatile("ldmatrix.sync.aligned.m8n8.x4.trans.shared.b16 {%0,%1,%2,%3}, [%4];"
                 : "=r"(r[0]), "=r"(r[1]), "=r"(r[2]), "=r"(r[3]) : "r"(addr));
}
__device__ __forceinline__ void mma16(float* d, const uint32_t* a, const uint32_t* b) {
    asm volatile(
        "mma.sync.aligned.m16n8k16.row.col.f32.f16.f16.f32 "
        "{%0,%1,%2,%3},{%4,%5,%6,%7},{%8,%9},{%0,%1,%2,%3};\n"
        : "+f"(d[0]), "+f"(d[1]), "+f"(d[2]), "+f"(d[3])
        : "r"(a[0]), "r"(a[1]), "r"(a[2]), "r"(a[3]), "r"(b[0]), "r"(b[1]));
}
__device__ __forceinline__ uint32_t pk2h(float a, float b) {
    __half2 t = __floats2half2_rn(a, b);
    return *reinterpret_cast<uint32_t*>(&t);
}

extern __shared__ char dynsm[];

// ---------------------------------------------------------------------------
// GEMM, fp16, D = A*B'.
//  BTRANS=0 (NT): B is NxK k-contiguous. Tiles: 128 rows x 128 B,
//                 swizzle chunk16 ^= (row & 7).
//  BTRANS=1 (NN): B is KxN n-contiguous. Tile: 64 k-rows x 256 B,
//                 swizzle chunk16 ^= (k & 7); loaded with ldmatrix.trans.
// batched==0: blockIdx.z selects operand set. batched==1: z = batch index.
// mode: 2 exp epilogue: f16 out + row-sum partials
//       3 fp32 out * (1/rowsum), rowsum summed from partials in-epilogue
//       5 f16 out, batch-transposed [nb][l][e] (+bias)
//       6 f16 out, row-major (+bias)
// ---------------------------------------------------------------------------
struct GArgs {
    const __half* Ah[3];
    const __half* Bh[3];
    float* Cf[3]; __half* Ch[3];
    const float* bias[3];
    int mode[3];
    long long lda, ldb, ldc;
    long long sA, sB, sC;
    int K, batched;
    float ascale;
    float* part;
};

template <int BTRANS>
__global__ __launch_bounds__(256, 2) void gemm_f16(GArgs p)
{
    constexpr int AH_O = 0, BH_O = TILE_B;

    const uint32_t sbase = (uint32_t)__cvta_generic_to_shared(dynsm);
    const int tid = threadIdx.x, lane = tid & 31, warp = tid >> 5;
    const int wm = warp & 1, wn = warp >> 1;      // 2(m) x 4(n) warps
    const int q = lane & 3, g = lane >> 2;

    const int zi = p.batched ? 0 : (int)blockIdx.z;
    const long long bz = p.batched ? (long long)blockIdx.z : 0;
    const int mode = p.mode[zi];

    const long long m0 = (long long)blockIdx.y * BM;
    const long long n0 = (long long)blockIdx.x * BN;

    const char* Ahb = (const char*)(p.Ah[zi] + bz * p.sA + m0 * p.lda);
    const char* Bhb = BTRANS
        ? (const char*)(p.Bh[zi] + bz * p.sB + n0)
        : (const char*)(p.Bh[zi] + bz * p.sB + n0 * p.ldb);

    // A ldmatrix lane addressing: row = a_row + i*16 (XOR lane-invariant).
    const int a_row = wm * 64 + (lane & 15);
    const int a_chb = lane >> 4;                   // chunk base (0/1) within 32B
    const uint32_t a_x = (uint32_t)(a_row & 7);
    // B NT lane addressing.
    const int b_row = wn * 32 + ((lane >> 4) & 1) * 8 + (lane & 7);
    const int b_chb = (lane >> 3) & 1;
    const uint32_t b_x = (uint32_t)(b_row & 7);
    // B NN (trans) lane addressing: k-row = kk*16 + (lane&15).
    const int bt_k = lane & 15;
    const uint32_t bt_x = (uint32_t)(lane & 7);

    float acc[4][4][4];
    #pragma unroll
    for (int i = 0; i < 4; ++i)
        #pragma unroll
        for (int j = 0; j < 4; ++j)
            #pragma unroll
            for (int r = 0; r < 4; ++r) acc[i][j][r] = 0.0f;

    const int KT = p.K / BK;                       // 16
    const long long lda2 = p.lda * 2, ldb2 = p.ldb * 2;

    auto load_tile = [&](int kt) {
        const uint32_t sb = sbase + (kt % NSTAGE) * STAGE_B;
        const long long kb = (long long)kt * (BK * 2);   // 128 B per K-chunk
        // A: 128 rows x 128 B; thread: row = tid>>3 (+32*pp), chunk c = tid&7
        const int r8 = tid >> 3, c8 = tid & 7;
        #pragma unroll
        for (int pp = 0; pp < 4; ++pp) {
            const int r = r8 + pp * 32;
            const uint32_t d = (uint32_t)(r * 128 + (((uint32_t)c8 ^ (r & 7)) << 4));
            cp16(sb + AH_O + d, Ahb + (long long)r * lda2 + kb + (c8 << 4));
        }
        if (BTRANS == 0) {
            #pragma unroll
            for (int pp = 0; pp < 4; ++pp) {
                const int r = r8 + pp * 32;
                const uint32_t d = (uint32_t)(r * 128 + (((uint32_t)c8 ^ (r & 7)) << 4));
                cp16(sb + BH_O + d, Bhb + (long long)r * ldb2 + kb + (c8 << 4));
            }
        } else {
            // B: 64 k-rows x 256 B (16 chunks), chunk ^= (k & 7). 1024 chunks.
            #pragma unroll
            for (int pp = 0; pp < 4; ++pp) {
                const int c = tid + pp * 256;
                const int k = c >> 4, c16 = c & 15;
                const uint32_t d = (uint32_t)(k * 256 + (((uint32_t)c16 ^ (k & 7)) << 4));
                cp16(sb + BH_O + d,
                     Bhb + (long long)(kt * BK + k) * ldb2 + ((long long)c16 << 4));
            }
        }
        cp_commit();
    };

    auto compute = [&](int kt) {
        const uint32_t sb = sbase + (kt % NSTAGE) * STAGE_B;
        #pragma unroll
        for (int kk = 0; kk < 4; ++kk) {
            const uint32_t cha = (uint32_t)(kk * 2 + a_chb);
            const uint32_t aoff = (uint32_t)(a_row * 128) + ((cha ^ a_x) << 4);
            uint32_t ah[4][4];
            #pragma unroll
            for (int i = 0; i < 4; ++i)
                ldsm4(ah[i], sb + AH_O + aoff + i * 2048);
            uint32_t bh[4][2];
            if (BTRANS == 0) {
                const uint32_t chb = (uint32_t)(kk * 2 + b_chb);
                const uint32_t boff = (uint32_t)(b_row * 128) + ((chb ^ b_x) << 4);
                #pragma unroll
                for (int jp = 0; jp < 2; ++jp) {
                    uint32_t rb[4];
                    ldsm4(rb, sb + BH_O + boff + jp * 2048);
                    bh[2*jp][0] = rb[0]; bh[2*jp][1] = rb[1];
                    bh[2*jp+1][0] = rb[2]; bh[2*jp+1][1] = rb[3];
                }
            } else {
                const uint32_t krow = (uint32_t)(kk * 16 + bt_k) * 256;
                #pragma unroll
                for (int jp = 0; jp < 2; ++jp) {
                    const uint32_t ch = (uint32_t)(wn * 4 + jp * 2 + (lane >> 4));
                    uint32_t rb[4];
                    ldsm4t(rb, sb + BH_O + krow + ((ch ^ bt_x) << 4));
                    bh[2*jp][0] = rb[0]; bh[2*jp][1] = rb[1];
                    bh[2*jp+1][0] = rb[2]; bh[2*jp+1][1] = rb[3];
                }
            }
            #pragma unroll
            for (int i = 0; i < 4; ++i)
                #pragma unroll
                for (int j = 0; j < 4; ++j)
                    mma16(acc[i][j], ah[i], bh[j]);
        }
    };

    // 3-stage pipeline, prefetch distance 2.
    load_tile(0);
    load_tile(1);
    for (int kt = 0; kt < KT; ++kt) {
        cp_wait<1>();
        __syncthreads();
        if (kt + 2 < KT) load_tile(kt + 2);
        else             cp_commit();
        compute(kt);
    }

    // ---------------- epilogues ----------------
    if (mode == 2) {
        __syncthreads();
        float (*srows)[4] = reinterpret_cast<float(*)[4]>(dynsm);
        __half* Ch = p.Ch[zi];
        #pragma unroll
        for (int i = 0; i < 4; ++i) {
            float p0 = 0.0f, p1 = 0.0f;
            const long long r0 = m0 + wm * 64 + i * 16 + g;
            #pragma unroll
            for (int j = 0; j < 4; ++j) {
                float e0 = __expf(acc[i][j][0] * p.ascale);
                float e1 = __expf(acc[i][j][1] * p.ascale);
                float e2 = __expf(acc[i][j][2] * p.ascale);
                float e3 = __expf(acc[i][j][3] * p.ascale);
                p0 += e0 + e1;  p1 += e2 + e3;
                const long long c0 = n0 + wn * 32 + j * 8 + 2 * q;
                *(uint32_t*)(Ch + bz * p.sC + r0 * p.ldc + c0)       = pk2h(e0, e1);
                *(uint32_t*)(Ch + bz * p.sC + (r0 + 8) * p.ldc + c0) = pk2h(e2, e3);
            }
            p0 += __shfl_xor_sync(0xFFFFFFFFu, p0, 1);
            p0 += __shfl_xor_sync(0xFFFFFFFFu, p0, 2);
            p1 += __shfl_xor_sync(0xFFFFFFFFu, p1, 1);
            p1 += __shfl_xor_sync(0xFFFFFFFFu, p1, 2);
            if (q == 0) {
                srows[wm * 64 + i * 16 + g][wn]     = p0;
                srows[wm * 64 + i * 16 + g + 8][wn] = p1;
            }
        }
        __syncthreads();
        if (tid < 128) {
            float s = srows[tid][0] + srows[tid][1] + srows[tid][2] + srows[tid][3];
            p.part[((bz << 10) + m0 + tid) * 8 + blockIdx.x] = s;
        }
        return;
    }

    if (mode == 3) {
        float* Cf = p.Cf[zi];
        #pragma unroll
        for (int i = 0; i < 4; ++i) {
            const long long r0 = m0 + wm * 64 + i * 16 + g;
            const float4 pa0 = ((const float4*)p.part)[((bz << 10) + r0) * 2];
            const float4 pb0 = ((const float4*)p.part)[((bz << 10) + r0) * 2 + 1];
            const float4 pa1 = ((const float4*)p.part)[((bz << 10) + r0 + 8) * 2];
            const float4 pb1 = ((const float4*)p.part)[((bz << 10) + r0 + 8) * 2 + 1];
            const float rs0 = 1.0f / (((pa0.x + pa0.y) + (pa0.z + pa0.w)) +
                                      ((pb0.x + pb0.y) + (pb0.z + pb0.w)));
            const float rs1 = 1.0f / (((pa1.x + pa1.y) + (pa1.z + pa1.w)) +
                                      ((pb1.x + pb1.y) + (pb1.z + pb1.w)));
            #pragma unroll
            for (int j = 0; j < 4; ++j) {
                const long long c0 = n0 + wn * 32 + j * 8 + 2 * q;
                *(float2*)(Cf + bz * p.sC + r0 * p.ldc + c0) =
                    make_float2(acc[i][j][0] * rs0, acc[i][j][1] * rs0);
                *(float2*)(Cf + bz * p.sC + (r0 + 8) * p.ldc + c0) =
                    make_float2(acc[i][j][2] * rs1, acc[i][j][3] * rs1);
            }
        }
        return;
    }

    // modes 5 / 6: f16 out, f = acc + bias
    const float* bias = p.bias[zi];
    __half* Ch = p.Ch[zi];
    #pragma unroll
    for (int i = 0; i < 4; ++i) {
        const long long r0 = m0 + wm * 64 + i * 16 + g;
        const long long r1 = r0 + 8;
        long long t0, t1;
        if (mode == 5) {    // batch-transposed [nb][l][e]
            t0 = ((r0 & 15) << 20) + ((r0 >> 4) << 10);
            t1 = ((r1 & 15) << 20) + ((r1 >> 4) << 10);
        } else {            // row-major
            t0 = r0 * p.ldc;
            t1 = r1 * p.ldc;
        }
        #pragma unroll
        for (int j = 0; j < 4; ++j) {
            const long long c0 = n0 + wn * 32 + j * 8 + 2 * q;
            const float b0 = bias[c0];
            const float b1 = bias[c0 + 1];
            *(uint32_t*)(Ch + t0 + c0) = pk2h(acc[i][j][0] + b0, acc[i][j][1] + b1);
            *(uint32_t*)(Ch + t1 + c0) = pk2h(acc[i][j][2] + b0, acc[i][j][3] + b1);
        }
    }
}

// ---------------------------------------------------------------------------
// fp32 -> f16, 3 arrays fused via blockIdx.y; 4 float4 per thread (MLP=4).
// n per array must be a multiple of 4096.
// ---------------------------------------------------------------------------
struct ConvArgs {
    const float* x[3];
    __half* h[3];
};

__global__ __launch_bounds__(256) void convert3_kernel(ConvArgs args)
{
    const int a = blockIdx.y;
    const float4* src = (const float4*)args.x[a];
    uint2* dst = (uint2*)args.h[a];
    const long long i0 = (long long)blockIdx.x * 1024 + threadIdx.x;
    float4 v0 = src[i0];
    float4 v1 = src[i0 + 256];
    float4 v2 = src[i0 + 512];
    float4 v3 = src[i0 + 768];
    dst[i0]       = make_uint2(pk2h(v0.x, v0.y), pk2h(v0.z, v0.w));
    dst[i0 + 256] = make_uint2(pk2h(v1.x, v1.y), pk2h(v1.z, v1.w));
    dst[i0 + 512] = make_uint2(pk2h(v2.x, v2.y), pk2h(v2.z, v2.w));
    dst[i0 + 768] = make_uint2(pk2h(v3.x, v3.y), pk2h(v3.z, v3.w));
}

// ---------------------------------------------------------------------------
// Launch
// ---------------------------------------------------------------------------
extern "C" void kernel_launch(void* const* d_in, const int* in_sizes, int n_in,
                              void* d_out, int out_size)
{
    const float* query = (const float*)d_in[0];
    const float* key   = (const float*)d_in[1];
    const float* value = (const float*)d_in[2];
    const float* wq    = (const float*)d_in[3];
    const float* wk    = (const float*)d_in[4];
    const float* wv    = (const float*)d_in[5];
    const float* bias  = (const float*)d_in[6];
    float* out = (float*)d_out;

    __half *xqh,*xkh,*xvh, *wqh,*wkh,*wvh;
    __half *qh,*kh,*vh,*ath;
    float *part;
    cudaGetSymbolAddress((void**)&xqh, g_xq_h);
    cudaGetSymbolAddress((void**)&xkh, g_xk_h);
    cudaGetSymbolAddress((void**)&xvh, g_xv_h);
    cudaGetSymbolAddress((void**)&wqh, g_wq_h);
    cudaGetSymbolAddress((void**)&wkh, g_wk_h);
    cudaGetSymbolAddress((void**)&wvh, g_wv_h);
    cudaGetSymbolAddress((void**)&qh,  g_q_h);
    cudaGetSymbolAddress((void**)&kh,  g_k_h);
    cudaGetSymbolAddress((void**)&vh,  g_v_h);
    cudaGetSymbolAddress((void**)&ath, g_a_h);
    cudaGetSymbolAddress((void**)&part, g_part);

    cudaFuncSetAttribute(gemm_f16<0>, cudaFuncAttributeMaxDynamicSharedMemorySize, SMEM_REQ);
    cudaFuncSetAttribute(gemm_f16<1>, cudaFuncAttributeMaxDynamicSharedMemorySize, SMEM_REQ);

    const long long MM = 1024LL * 1024;

    // 1) inputs and weights -> f16
    {
        ConvArgs in;
        in.x[0] = query; in.h[0] = xqh;
        in.x[1] = key;   in.h[1] = xkh;
        in.x[2] = value; in.h[2] = xvh;
        convert3_kernel<<<dim3(4096, 3), 256>>>(in);
        ConvArgs w;
        w.x[0] = wq; w.h[0] = wqh;
        w.x[1] = wk; w.h[1] = wkh;
        w.x[2] = wv; w.h[2] = wvh;
        convert3_kernel<<<dim3(256, 3), 256>>>(w);
    }

    // 2) merged projections: f = acc + bias
    //    q, k -> f16 batch-major (mode 5); v -> f16 row-major (mode 6).
    {
        GArgs a = {};
        a.Ah[0] = xqh; a.Bh[0] = wqh;
        a.Ah[1] = xkh; a.Bh[1] = wkh;
        a.Ah[2] = xvh; a.Bh[2] = wvh;
        a.Ch[0] = qh;
        a.Ch[1] = kh;
        a.Ch[2] = vh;
        a.bias[0] = bias; a.bias[1] = bias + 1024; a.bias[2] = bias + 2048;
        a.mode[0] = 5; a.mode[1] = 5; a.mode[2] = 6;
        a.lda = 1024; a.ldb = 1024; a.ldc = 1024;
        a.sA = 0; a.sB = 0; a.sC = 0;
        a.K = 1024; a.batched = 0; a.ascale = 1.0f;
        gemm_f16<0><<<dim3(8, 128, 3), 256, SMEM_REQ>>>(a);
    }

    // 3) scores (fp16) + fused exp/partial-rowsum
    {
        GArgs a = {};
        a.Ah[0] = qh; a.Bh[0] = kh;
        a.Ch[0] = ath;
        a.mode[0] = 2;
        a.lda = 1024; a.ldb = 1024; a.ldc = 1024;
        a.sA = 1LL << 20; a.sB = 1LL << 20; a.sC = MM;
        a.K = 1024; a.batched = 1; a.ascale = 1.0f / 32.0f;
        a.part = part;
        gemm_f16<0><<<dim3(8, 8, 16), 256, SMEM_REQ>>>(a);
    }

    // 4) out = (e @ V) * (1/rowsum)  — NN path reads V directly, rowsum fused
    {
        GArgs a = {};
        a.Ah[0] = ath; a.Bh[0] = vh;
        a.Cf[0] = out;
        a.mode[0] = 3;
        a.lda = 1024; a.ldb = 16384; a.ldc = 16384;
        a.sA = MM; a.sB = 1024; a.sC = 1024;
        a.K = 1024; a.batched = 1; a.ascale = 1.0f;
        a.part = part;
        gemm_f16<1><<<dim3(8, 8, 16), 256, SMEM_REQ>>>(a);
    }
}